// round 13
// baseline (speedup 1.0000x reference)
#include <cuda_runtime.h>

#define NB 8
#define PP 2304
#define QTOT (NB*PP)       // 18432
#define CIN 64
#define OUTC 384
#define NSTRIDE (OUTC*PP)
#define SLICE (64*PP)
#define NS 9               // split-K factor for visual attention
#define COLW 56            // (qkv0 only) smem row width

// Scratch (allocation-free rule: __device__ globals)
__device__ float g_q[NB*8*PP];
__device__ float g_k[NB*8*PP];
__device__ float g_v[NB*32*PP];
__device__ float g_pl[NS*QTOT];
__device__ float g_pv[NS*32*QTOT];   // [split][c][q] — warp-coalesced (round-11 layout)
__device__ float g_x[QTOT*64];       // [p][n][c] mega-kernel input
__device__ float g_wt[5*4096];       // per head: [64][48] qkv-T (3072) + [32][32] conv-T (1024)

typedef unsigned long long u64;

__device__ __forceinline__ u64 fma2(u64 a,u64 b,u64 c){u64 d;asm("fma.rn.f32x2 %0,%1,%2,%3;":"=l"(d):"l"(a),"l"(b),"l"(c));return d;}
__device__ __forceinline__ u64 add2(u64 a,u64 b){u64 d;asm("add.rn.f32x2 %0,%1,%2;":"=l"(d):"l"(a),"l"(b));return d;}
__device__ __forceinline__ u64 pack2(float lo,float hi){u64 d;asm("mov.b64 %0,{%1,%2};":"=l"(d):"f"(lo),"f"(hi));return d;}
__device__ __forceinline__ void unpack2(u64 v,float&lo,float&hi){asm("mov.b64 {%0,%1},%2;":"=f"(lo),"=f"(hi):"l"(v));}

__device__ __forceinline__ float dot4(float4 a, float4 b){
    return a.x*b.x + a.y*b.y + a.z*b.z + a.w*b.w;
}

// ---------------------------------------------------------------------------
// One-shot weight transpose: [o][c] (gmem) -> [c][o] flat per head in g_wt.
// ---------------------------------------------------------------------------
__global__ __launch_bounds__(256) void transpose_w(
    const float* __restrict__ tq_w, const float* __restrict__ tk_w,
    const float* __restrict__ tv_w, const float* __restrict__ tc_w)
{
    int i = blockIdx.x*256 + threadIdx.x;
    if (i >= 5*4096) return;
    int h = i >> 12, r = i & 4095;
    float v;
    if (r < 3072) {
        int c = r / 48, o = r % 48;
        v = (o<8)  ? tq_w[h*512  + o*64 + c]
          : (o<16) ? tk_w[h*512  + (o-8)*64 + c]
                   : tv_w[h*2048 + (o-16)*64 + c];
    } else {
        int rr = r - 3072;
        int c = rr >> 5, o = rr & 31;
        v = tc_w[h*1024 + o*32 + c];
    }
    g_wt[i] = v;
}

// ---------------------------------------------------------------------------
// Stage-0 QKV, 4-way split (unchanged).
// ---------------------------------------------------------------------------
__global__ __launch_bounds__(128) void qkv0_kernel(
    const float* __restrict__ src,
    const float* __restrict__ qw, const float* __restrict__ qb,
    const float* __restrict__ kw, const float* __restrict__ kb,
    const float* __restrict__ vw, const float* __restrict__ vb)
{
    __shared__ alignas(16) float swt[64*52];
    __shared__ alignas(16) float sbs[48];
    __shared__ alignas(16) float xsm[64*COLW];

    const int tid = threadIdx.x;
    const int wq = tid >> 5, l = tid & 31;
    const int pos = l & 3, n = l >> 2;
    const int col = 8 + pos*12 + n;
    const int pg = blockIdx.x*4;

    for (int i = tid; i < 48*64; i += 128) {
        int o = i >> 6, c = i & 63;
        float wv = (o<8) ? qw[o*64+c] : (o<16) ? kw[(o-8)*64+c] : vw[(o-16)*64+c];
        swt[c*52 + o] = wv;
    }
    if (tid < 48) sbs[tid] = (tid<8)? qb[tid] : (tid<16? kb[tid-8] : vb[tid-16]);
    for (int i = tid; i < 64*32; i += 128) {
        int c = i >> 5, ce = i & 31;
        int pp_ = ce & 3, nn = ce >> 2;
        xsm[c*COLW + (8 + pp_*12 + nn)] = src[(long)nn*CIN*PP + (long)c*PP + pg + pp_];
    }
    __syncthreads();

    u64 acc[6];
    {
        const u64* bp = (const u64*)sbs;
        #pragma unroll
        for (int t=0;t<6;t++) acc[t] = bp[wq*6 + t];
    }
    #pragma unroll 8
    for (int c=0;c<64;c++) {
        float xv = xsm[c*COLW + col];
        u64 x2 = pack2(xv,xv);
        const ulonglong2* wr = (const ulonglong2*)(swt + c*52 + wq*12);
        ulonglong2 w0 = wr[0], w1 = wr[1], w2 = wr[2];
        acc[0]=fma2(x2,w0.x,acc[0]); acc[1]=fma2(x2,w0.y,acc[1]);
        acc[2]=fma2(x2,w1.x,acc[2]); acc[3]=fma2(x2,w1.y,acc[3]);
        acc[4]=fma2(x2,w2.x,acc[4]); acc[5]=fma2(x2,w2.y,acc[5]);
    }
    float o12[12];
    #pragma unroll
    for (int t=0;t<6;t++) unpack2(acc[t], o12[2*t], o12[2*t+1]);
    const int p = pg + pos;
    #pragma unroll
    for (int t=0;t<12;t++) {
        int o = wq*12 + t;
        if (o < 8)       g_q[(n*8  + o     )*PP + p] = o12[t];
        else if (o < 16) g_k[(n*8  + (o-8) )*PP + p] = o12[t];
        else             g_v[(n*32 + (o-16))*PP + p] = fmaxf(o12[t], 0.f);
    }
}

// ---------------------------------------------------------------------------
// Visual attention, split-K. K/V smem stored as u64 PAIRS per key:
// ksu2[rp][j][2], vsu2[tp][j][2] (row pitch 258 u64). Inner-loop reads are
// warp-uniform broadcast LDS.128 (10 loads/j vs 20); fills are STS.128 at
// lane-stride 16B (contiguous, conflict-free — audited).
// ---------------------------------------------------------------------------
__global__ __launch_bounds__(128) void vis_attn_split(void)
{
    __shared__ alignas(16) u64 ksu2[2*258];    // [rp][j*2 + half]
    __shared__ alignas(16) u64 vsu2[8*258];    // [tp][j*2 + half]
    const int tid = threadIdx.x;
    const int tile = blockIdx.x / NS, split = blockIdx.x % NS;
    const int n = tile / 6, tw = tile % 6;
    const int qp = tw*384 + tid;
    const float* qb_ = g_q + n*8*PP;
    const float* kb_ = g_k + n*8*PP;
    const float* vb_ = g_v + n*32*PP;

    u64 qr[3][4];
    #pragma unroll
    for (int i=0;i<3;i++)
        #pragma unroll
        for (int r=0;r<4;r++)
            qr[i][r] = pack2(qb_[(2*r)*PP + qp + i*128], qb_[(2*r+1)*PP + qp + i*128]);

    float l[3] = {0.f, 0.f, 0.f};
    u64 vacc[3][16];
    #pragma unroll
    for (int i=0;i<3;i++)
        #pragma unroll
        for (int t=0;t<16;t++) vacc[i][t] = 0ULL;

    const u64 z = 0ULL;
    for (int ch = split*2; ch < split*2 + 2; ch++) {
        __syncthreads();
        const int base = ch*128 + tid;
        #pragma unroll
        for (int rp=0;rp<2;rp++) {
            ulonglong2 kv;
            kv.x = pack2(kb_[(4*rp  )*PP+base], kb_[(4*rp+1)*PP+base]);
            kv.y = pack2(kb_[(4*rp+2)*PP+base], kb_[(4*rp+3)*PP+base]);
            *(ulonglong2*)(ksu2 + rp*258 + tid*2) = kv;
        }
        #pragma unroll
        for (int tp=0;tp<8;tp++) {
            ulonglong2 vv;
            vv.x = pack2(vb_[(4*tp  )*PP+base], vb_[(4*tp+1)*PP+base]);
            vv.y = pack2(vb_[(4*tp+2)*PP+base], vb_[(4*tp+3)*PP+base]);
            *(ulonglong2*)(vsu2 + tp*258 + tid*2) = vv;
        }
        __syncthreads();
        #pragma unroll 2
        for (int j=0;j<128;j++) {
            ulonglong2 ka = *(const ulonglong2*)(ksu2 + j*2);
            ulonglong2 kb2 = *(const ulonglong2*)(ksu2 + 258 + j*2);
            float pr[3];
            #pragma unroll
            for (int i=0;i<3;i++) {
                u64 d = add2(fma2(qr[i][0],ka.x,fma2(qr[i][1],ka.y,z)),
                             fma2(qr[i][2],kb2.x,fma2(qr[i][3],kb2.y,z)));
                float lo,hi; unpack2(d,lo,hi);
                pr[i] = __expf(lo + hi);
                l[i] += pr[i];
            }
            u64 p0 = pack2(pr[0],pr[0]), p1 = pack2(pr[1],pr[1]), p2 = pack2(pr[2],pr[2]);
            #pragma unroll
            for (int tp=0;tp<8;tp++) {
                ulonglong2 vv = *(const ulonglong2*)(vsu2 + tp*258 + j*2);
                vacc[0][2*tp]   = fma2(p0, vv.x, vacc[0][2*tp]);
                vacc[1][2*tp]   = fma2(p1, vv.x, vacc[1][2*tp]);
                vacc[2][2*tp]   = fma2(p2, vv.x, vacc[2][2*tp]);
                vacc[0][2*tp+1] = fma2(p0, vv.y, vacc[0][2*tp+1]);
                vacc[1][2*tp+1] = fma2(p1, vv.y, vacc[1][2*tp+1]);
                vacc[2][2*tp+1] = fma2(p2, vv.y, vacc[2][2*tp+1]);
            }
        }
    }
    #pragma unroll
    for (int i=0;i<3;i++) {
        int q = n*PP + qp + i*128;
        g_pl[split*QTOT + q] = l[i];
        #pragma unroll
        for (int t=0;t<16;t++) {
            float lo,hi; unpack2(vacc[i][t], lo, hi);
            g_pv[(split*32 + 2*t  )*QTOT + q] = lo;
            g_pv[(split*32 + 2*t+1)*QTOT + q] = hi;
        }
    }
}

// ---------------------------------------------------------------------------
// Combine v2 (round-11 version, 4 threads/position, warp-coalesced loads).
// ---------------------------------------------------------------------------
__global__ __launch_bounds__(128) void combine_kernel(
    const float* __restrict__ cw, const float* __restrict__ cb,
    float* __restrict__ out)
{
    __shared__ alignas(16) u64 cwt[32*16];    // [c][o2]
    __shared__ alignas(16) float cbs[32];
    __shared__ alignas(16) float avs[32*33];  // [cell][c], pitch 33
    const int tid = threadIdx.x;
    const int wq = tid >> 5, cell = tid & 31;

    for (int i = tid; i < 32*16; i += 128) {
        int c = i/16, t = i%16;
        cwt[i] = pack2(cw[(2*t)*32+c], cw[(2*t+1)*32+c]);
    }
    if (tid < 32) cbs[tid] = cb[tid];

    const int gid = blockIdx.x*32 + cell;
    const int n = gid/PP, p = gid%PP;

    float l = 0.f;
    #pragma unroll
    for (int sp=0; sp<NS; sp++) l += g_pl[sp*QTOT + gid];

    float va[8];
    #pragma unroll
    for (int j=0;j<8;j++) va[j] = 0.f;
    #pragma unroll
    for (int sp=0; sp<NS; sp++) {
        #pragma unroll
        for (int j=0;j<8;j++)
            va[j] += g_pv[(sp*32 + wq*8 + j)*QTOT + gid];
    }
    float inv = 1.f / l;
    #pragma unroll
    for (int j=0;j<8;j++) avs[cell*33 + wq*8 + j] = va[j] * inv;
    __syncthreads();

    u64 acc[4];
    {
        const u64* bp = (const u64*)cbs;
        #pragma unroll
        for (int t=0;t<4;t++) acc[t] = bp[wq*4 + t];
    }
    #pragma unroll 8
    for (int c=0;c<32;c++) {
        float av = avs[cell*33 + c];
        u64 x2 = pack2(av, av);
        const ulonglong2* wr = (const ulonglong2*)(cwt + c*16 + wq*4);
        ulonglong2 w0 = wr[0], w1 = wr[1];
        acc[0]=fma2(x2,w0.x,acc[0]); acc[1]=fma2(x2,w0.y,acc[1]);
        acc[2]=fma2(x2,w1.x,acc[2]); acc[3]=fma2(x2,w1.y,acc[3]);
    }
    float oc[8];
    #pragma unroll
    for (int t=0;t<4;t++) unpack2(acc[t], oc[2*t], oc[2*t+1]);

    float vv[8];
    #pragma unroll
    for (int j=0;j<8;j++) vv[j] = g_v[(n*32 + wq*8 + j)*PP + p];

    float* ob = out + (long)n*NSTRIDE + p;   // slice 0
    #pragma unroll
    for (int j=0;j<8;j++) {
        ob[(wq*8+j)*PP]      = oc[j];
        ob[(32+wq*8+j)*PP]   = vv[j];
    }

    float* xp = g_x + ((long)p*8 + n)*64;
    *(float4*)(xp + wq*8    ) = make_float4(oc[0],oc[1],oc[2],oc[3]);
    *(float4*)(xp + wq*8 + 4) = make_float4(oc[4],oc[5],oc[6],oc[7]);
    *(float4*)(xp + 32 + wq*8    ) = make_float4(vv[0],vv[1],vv[2],vv[3]);
    *(float4*)(xp + 32 + wq*8 + 4) = make_float4(vv[4],vv[5],vv[6],vv[7]);
}

// ---------------------------------------------------------------------------
// MEGA temporal v5 (unchanged from the 144 us version).
// ---------------------------------------------------------------------------
__global__ __launch_bounds__(128) void mega_temporal(
    const float* __restrict__ tq_b, const float* __restrict__ tk_b,
    const float* __restrict__ tv_b, const float* __restrict__ tc_b,
    float* __restrict__ out)
{
    __shared__ alignas(16) float swt[64*48];     // qkv weights [c][o] pitch 48
    __shared__ alignas(16) float cwt[32*32];     // conv weights [c][o] pitch 32
    __shared__ alignas(16) float sbs[48];
    __shared__ alignas(16) float cbs[32];
    __shared__ alignas(16) float xsm[64*68];     // head input [cell][c], pitch 68
    __shared__ alignas(16) float qkvsm[66*52];   // rows 0,1 = zero guards; row(cell)=2+cell

    const int tid  = threadIdx.x;
    const int wq   = tid >> 5, cp = tid & 31;
    const int posA = cp >> 3, n = cp & 7;
    const int cellA = cp, cellB = cp + 32;
    const int rowA = 2 + cellA, rowB = 2 + cellB;
    const int pg   = blockIdx.x*8;

    for (int i = tid; i < 66*52; i += 128) qkvsm[i] = 0.f;

    {
        const float* gA = g_x + ((long)(pg+posA  )*8 + n)*64 + wq*16;
        const float* gB = g_x + ((long)(pg+posA+4)*8 + n)*64 + wq*16;
        #pragma unroll
        for (int k=0;k<4;k++) {
            *(float4*)(xsm + cellA*68 + wq*16 + 4*k) = *(const float4*)(gA + 4*k);
            *(float4*)(xsm + cellB*68 + wq*16 + 4*k) = *(const float4*)(gB + 4*k);
        }
    }

    for (int h=0; h<5; h++) {
        __syncthreads();   // barrier A

        {
            const float4* wt4 = (const float4*)(g_wt + h*4096);
            float4* s4 = (float4*)swt;
            float4* c4p = (float4*)cwt;
            #pragma unroll
            for (int k=0;k<6;k++) s4[tid + 128*k] = wt4[tid + 128*k];
            #pragma unroll
            for (int k=0;k<2;k++) c4p[tid + 128*k] = wt4[768 + tid + 128*k];
        }
        if (tid < 48) sbs[tid] = (tid<8)? tq_b[h*8+tid] : (tid<16? tk_b[h*8+tid-8] : tv_b[h*32+tid-16]);
        if (tid < 32) cbs[tid] = tc_b[h*32+tid];
        __syncthreads();   // barrier B

        u64 accA[6], accB[6];
        {
            const u64* bp = (const u64*)sbs;
            #pragma unroll
            for (int t=0;t<6;t++) { accA[t] = bp[wq*6 + t]; accB[t] = accA[t]; }
        }
        #pragma unroll
        for (int c4=0; c4<64; c4+=4) {
            float4 xa = *(const float4*)(xsm + cellA*68 + c4);
            float4 xb = *(const float4*)(xsm + cellB*68 + c4);
            float xas[4] = {xa.x, xa.y, xa.z, xa.w};
            float xbs[4] = {xb.x, xb.y, xb.z, xb.w};
            #pragma unroll
            for (int j=0;j<4;j++) {
                u64 x2a = pack2(xas[j], xas[j]);
                u64 x2b = pack2(xbs[j], xbs[j]);
                const ulonglong2* wr = (const ulonglong2*)(swt + (c4+j)*48 + wq*12);
                ulonglong2 w0 = wr[0], w1 = wr[1], w2 = wr[2];
                accA[0]=fma2(x2a,w0.x,accA[0]); accA[1]=fma2(x2a,w0.y,accA[1]);
                accA[2]=fma2(x2a,w1.x,accA[2]); accA[3]=fma2(x2a,w1.y,accA[3]);
                accA[4]=fma2(x2a,w2.x,accA[4]); accA[5]=fma2(x2a,w2.y,accA[5]);
                accB[0]=fma2(x2b,w0.x,accB[0]); accB[1]=fma2(x2b,w0.y,accB[1]);
                accB[2]=fma2(x2b,w1.x,accB[2]); accB[3]=fma2(x2b,w1.y,accB[3]);
                accB[4]=fma2(x2b,w2.x,accB[4]); accB[5]=fma2(x2b,w2.y,accB[5]);
            }
        }
        {
            float oA[12], oB[12];
            #pragma unroll
            for (int t=0;t<6;t++) { unpack2(accA[t], oA[2*t], oA[2*t+1]);
                                    unpack2(accB[t], oB[2*t], oB[2*t+1]); }
            #pragma unroll
            for (int t=0;t<12;t++) if (12*wq + t >= 16) {
                oA[t] = fmaxf(oA[t], 0.f); oB[t] = fmaxf(oB[t], 0.f);
            }
            float* ra = qkvsm + rowA*52 + wq*12;
            float* rb = qkvsm + rowB*52 + wq*12;
            *(float4*)(ra  ) = make_float4(oA[0],oA[1],oA[2],oA[3]);
            *(float4*)(ra+4) = make_float4(oA[4],oA[5],oA[6],oA[7]);
            *(float4*)(ra+8) = make_float4(oA[8],oA[9],oA[10],oA[11]);
            *(float4*)(rb  ) = make_float4(oB[0],oB[1],oB[2],oB[3]);
            *(float4*)(rb+4) = make_float4(oB[4],oB[5],oB[6],oB[7]);
            *(float4*)(rb+8) = make_float4(oB[8],oB[9],oB[10],oB[11]);
        }
        __syncthreads();   // barrier C

        float a0A,a1A,a2A, a0B,a1B,a2B;
        {
            const float* rp = qkvsm + rowA*52;
            float4 q0=*(const float4*)(rp),     q1=*(const float4*)(rp+4);
            float4 k0a=*(const float4*)(rp+8),  k0b=*(const float4*)(rp+12);
            float4 k1a=*(const float4*)(rp+8-52),  k1b=*(const float4*)(rp+12-52);
            float4 k2a=*(const float4*)(rp+8-104), k2b=*(const float4*)(rp+12-104);
            float l2 = dot4(q0,k0a)+dot4(q1,k0b);
            float l1 = (n>=1) ? dot4(q0,k1a)+dot4(q1,k1b) : 0.f;
            float l0 = (n>=2) ? dot4(q0,k2a)+dot4(q1,k2b) : 0.f;
            float m  = fmaxf(l0, fmaxf(l1, l2));
            float e0=__expf(l0-m), e1=__expf(l1-m), e2=__expf(l2-m);
            float inv = 1.f/(e0+e1+e2);
            a2A = e2*inv;
            a1A = (n>=1) ? e1*inv : 0.f;
            a0A = (n>=2) ? e0*inv : 0.f;
        }
        {
            const float* rp = qkvsm + rowB*52;
            float4 q0=*(const float4*)(rp),     q1=*(const float4*)(rp+4);
            float4 k0a=*(const float4*)(rp+8),  k0b=*(const float4*)(rp+12);
            float4 k1a=*(const float4*)(rp+8-52),  k1b=*(const float4*)(rp+12-52);
            float4 k2a=*(const float4*)(rp+8-104), k2b=*(const float4*)(rp+12-104);
            float l2 = dot4(q0,k0a)+dot4(q1,k0b);
            float l1 = (n>=1) ? dot4(q0,k1a)+dot4(q1,k1b) : 0.f;
            float l0 = (n>=2) ? dot4(q0,k2a)+dot4(q1,k2b) : 0.f;
            float m  = fmaxf(l0, fmaxf(l1, l2));
            float e0=__expf(l0-m), e1=__expf(l1-m), e2=__expf(l2-m);
            float inv = 1.f/(e0+e1+e2);
            a2B = e2*inv;
            a1B = (n>=1) ? e1*inv : 0.f;
            a0B = (n>=2) ? e0*inv : 0.f;
        }

        u64 cA[4], cB[4];
        {
            const u64* bp = (const u64*)cbs;
            #pragma unroll
            for (int t=0;t<4;t++) { cA[t] = bp[wq*4 + t]; cB[t] = cA[t]; }
        }
        #pragma unroll
        for (int c4=0; c4<32; c4+=4) {
            const float* vra = qkvsm + rowA*52 + 16 + c4;
            const float* vrb = qkvsm + rowB*52 + 16 + c4;
            float4 v0a=*(const float4*)(vra), v1a=*(const float4*)(vra-52), v2a=*(const float4*)(vra-104);
            float4 v0b=*(const float4*)(vrb), v1b=*(const float4*)(vrb-52), v2b=*(const float4*)(vrb-104);
            float avA[4], avB[4];
            avA[0]=a2A*v0a.x+a1A*v1a.x+a0A*v2a.x; avA[1]=a2A*v0a.y+a1A*v1a.y+a0A*v2a.y;
            avA[2]=a2A*v0a.z+a1A*v1a.z+a0A*v2a.z; avA[3]=a2A*v0a.w+a1A*v1a.w+a0A*v2a.w;
            avB[0]=a2B*v0b.x+a1B*v1b.x+a0B*v2b.x; avB[1]=a2B*v0b.y+a1B*v1b.y+a0B*v2b.y;
            avB[2]=a2B*v0b.z+a1B*v1b.z+a0B*v2b.z; avB[3]=a2B*v0b.w+a1B*v1b.w+a0B*v2b.w;
            #pragma unroll
            for (int j=0;j<4;j++) {
                u64 x2a = pack2(avA[j], avA[j]);
                u64 x2b = pack2(avB[j], avB[j]);
                const ulonglong2* wr = (const ulonglong2*)(cwt + (c4+j)*32 + wq*8);
                ulonglong2 w0 = wr[0], w1 = wr[1];
                cA[0]=fma2(x2a,w0.x,cA[0]); cA[1]=fma2(x2a,w0.y,cA[1]);
                cA[2]=fma2(x2a,w1.x,cA[2]); cA[3]=fma2(x2a,w1.y,cA[3]);
                cB[0]=fma2(x2b,w0.x,cB[0]); cB[1]=fma2(x2b,w0.y,cB[1]);
                cB[2]=fma2(x2b,w1.x,cB[2]); cB[3]=fma2(x2b,w1.y,cB[3]);
            }
        }
        {
            float ocA[8], ocB[8];
            #pragma unroll
            for (int t=0;t<4;t++) { unpack2(cA[t], ocA[2*t], ocA[2*t+1]);
                                    unpack2(cB[t], ocB[2*t], ocB[2*t+1]); }
            float4 vaA = *(const float4*)(qkvsm + rowA*52 + 16 + wq*8);
            float4 vbA = *(const float4*)(qkvsm + rowA*52 + 16 + wq*8 + 4);
            float4 vaB = *(const float4*)(qkvsm + rowB*52 + 16 + wq*8);
            float4 vbB = *(const float4*)(qkvsm + rowB*52 + 16 + wq*8 + 4);
            float vqA[8] = {vaA.x,vaA.y,vaA.z,vaA.w, vbA.x,vbA.y,vbA.z,vbA.w};
            float vqB[8] = {vaB.x,vaB.y,vaB.z,vaB.w, vbB.x,vbB.y,vbB.z,vbB.w};

            float* obA = out + (long)n*NSTRIDE + (long)(h+1)*SLICE + pg + posA;
            float* obB = obA + 4;
            #pragma unroll
            for (int j=0;j<8;j++) {
                obA[(8*wq+j)*PP]    = ocA[j];
                obA[(32+8*wq+j)*PP] = vqA[j];
                obB[(8*wq+j)*PP]    = ocB[j];
                obB[(32+8*wq+j)*PP] = vqB[j];
            }
            float* xrA = xsm + cellA*68;
            float* xrB = xsm + cellB*68;
            *(float4*)(xrA + 8*wq    ) = make_float4(ocA[0],ocA[1],ocA[2],ocA[3]);
            *(float4*)(xrA + 8*wq + 4) = make_float4(ocA[4],ocA[5],ocA[6],ocA[7]);
            *(float4*)(xrA + 32 + 8*wq    ) = vaA;
            *(float4*)(xrA + 32 + 8*wq + 4) = vbA;
            *(float4*)(xrB + 8*wq    ) = make_float4(ocB[0],ocB[1],ocB[2],ocB[3]);
            *(float4*)(xrB + 8*wq + 4) = make_float4(ocB[4],ocB[5],ocB[6],ocB[7]);
            *(float4*)(xrB + 32 + 8*wq    ) = vaB;
            *(float4*)(xrB + 32 + 8*wq + 4) = vbB;
        }
    }
}

// ---------------------------------------------------------------------------
extern "C" void kernel_launch(void* const* d_in, const int* in_sizes, int n_in,
                              void* d_out, int out_size)
{
    const float* x    = (const float*)d_in[0];
    const float* vq_w = (const float*)d_in[1];
    const float* vq_b = (const float*)d_in[2];
    const float* vk_w = (const float*)d_in[3];
    const float* vk_b = (const float*)d_in[4];
    const float* vv_w = (const float*)d_in[5];
    const float* vv_b = (const float*)d_in[6];
    const float* vc_w = (const float*)d_in[7];
    const float* vc_b = (const float*)d_in[8];
    const float* tq_w = (const float*)d_in[9];
    const float* tq_b = (const float*)d_in[10];
    const float* tk_w = (const float*)d_in[11];
    const float* tk_b = (const float*)d_in[12];
    const float* tv_w = (const float*)d_in[13];
    const float* tv_b = (const float*)d_in[14];
    const float* tc_w = (const float*)d_in[15];
    const float* tc_b = (const float*)d_in[16];
    float* out = (float*)d_out;

    transpose_w<<<80,256>>>(tq_w, tk_w, tv_w, tc_w);
    qkv0_kernel<<<576,128>>>(x, vq_w, vq_b, vk_w, vk_b, vv_w, vv_b);
    vis_attn_split<<<48*NS,128>>>();
    combine_kernel<<<576,128>>>(vc_w, vc_b, out);
    mega_temporal<<<288,128>>>(tq_b, tk_b, tv_b, tc_b, out);
}

// round 14
// speedup vs baseline: 1.0560x; 1.0560x over previous
#include <cuda_runtime.h>

#define NB 8
#define PP 2304
#define QTOT (NB*PP)       // 18432
#define CIN 64
#define OUTC 384
#define NSTRIDE (OUTC*PP)
#define SLICE (64*PP)
#define NS 9               // split-K factor for visual attention
#define COLW 56            // (qkv0 only) smem row width

// Scratch (allocation-free rule: __device__ globals)
__device__ float g_q[NB*8*PP];
__device__ float g_k[NB*8*PP];
__device__ float g_v[NB*32*PP];
__device__ float g_pl[NS*QTOT];
__device__ float g_pv[NS*32*QTOT];   // [split][c][q] — warp-coalesced
__device__ float g_x[QTOT*64];       // [p][n][c] mega-kernel input
__device__ float g_wt[5*4096];       // per head: [64][48] qkv-T (3072) + [32][32] conv-T (1024)

typedef unsigned long long u64;

__device__ __forceinline__ u64 fma2(u64 a,u64 b,u64 c){u64 d;asm("fma.rn.f32x2 %0,%1,%2,%3;":"=l"(d):"l"(a),"l"(b),"l"(c));return d;}
__device__ __forceinline__ u64 add2(u64 a,u64 b){u64 d;asm("add.rn.f32x2 %0,%1,%2;":"=l"(d):"l"(a),"l"(b));return d;}
__device__ __forceinline__ u64 pack2(float lo,float hi){u64 d;asm("mov.b64 %0,{%1,%2};":"=l"(d):"f"(lo),"f"(hi));return d;}
__device__ __forceinline__ void unpack2(u64 v,float&lo,float&hi){asm("mov.b64 {%0,%1},%2;":"=f"(lo),"=f"(hi):"l"(v));}

__device__ __forceinline__ float dot4(float4 a, float4 b){
    return a.x*b.x + a.y*b.y + a.z*b.z + a.w*b.w;
}

// ---------------------------------------------------------------------------
// One-shot weight transpose: [o][c] (gmem) -> [c][o] flat per head in g_wt.
// ---------------------------------------------------------------------------
__global__ __launch_bounds__(256) void transpose_w(
    const float* __restrict__ tq_w, const float* __restrict__ tk_w,
    const float* __restrict__ tv_w, const float* __restrict__ tc_w)
{
    int i = blockIdx.x*256 + threadIdx.x;
    if (i >= 5*4096) return;
    int h = i >> 12, r = i & 4095;
    float v;
    if (r < 3072) {
        int c = r / 48, o = r % 48;
        v = (o<8)  ? tq_w[h*512  + o*64 + c]
          : (o<16) ? tk_w[h*512  + (o-8)*64 + c]
                   : tv_w[h*2048 + (o-16)*64 + c];
    } else {
        int rr = r - 3072;
        int c = rr >> 5, o = rr & 31;
        v = tc_w[h*1024 + o*32 + c];
    }
    g_wt[i] = v;
}

// ---------------------------------------------------------------------------
// Stage-0 QKV, 4-way split (unchanged).
// ---------------------------------------------------------------------------
__global__ __launch_bounds__(128) void qkv0_kernel(
    const float* __restrict__ src,
    const float* __restrict__ qw, const float* __restrict__ qb,
    const float* __restrict__ kw, const float* __restrict__ kb,
    const float* __restrict__ vw, const float* __restrict__ vb)
{
    __shared__ alignas(16) float swt[64*52];
    __shared__ alignas(16) float sbs[48];
    __shared__ alignas(16) float xsm[64*COLW];

    const int tid = threadIdx.x;
    const int wq = tid >> 5, l = tid & 31;
    const int pos = l & 3, n = l >> 2;
    const int col = 8 + pos*12 + n;
    const int pg = blockIdx.x*4;

    for (int i = tid; i < 48*64; i += 128) {
        int o = i >> 6, c = i & 63;
        float wv = (o<8) ? qw[o*64+c] : (o<16) ? kw[(o-8)*64+c] : vw[(o-16)*64+c];
        swt[c*52 + o] = wv;
    }
    if (tid < 48) sbs[tid] = (tid<8)? qb[tid] : (tid<16? kb[tid-8] : vb[tid-16]);
    for (int i = tid; i < 64*32; i += 128) {
        int c = i >> 5, ce = i & 31;
        int pp_ = ce & 3, nn = ce >> 2;
        xsm[c*COLW + (8 + pp_*12 + nn)] = src[(long)nn*CIN*PP + (long)c*PP + pg + pp_];
    }
    __syncthreads();

    u64 acc[6];
    {
        const u64* bp = (const u64*)sbs;
        #pragma unroll
        for (int t=0;t<6;t++) acc[t] = bp[wq*6 + t];
    }
    #pragma unroll 8
    for (int c=0;c<64;c++) {
        float xv = xsm[c*COLW + col];
        u64 x2 = pack2(xv,xv);
        const ulonglong2* wr = (const ulonglong2*)(swt + c*52 + wq*12);
        ulonglong2 w0 = wr[0], w1 = wr[1], w2 = wr[2];
        acc[0]=fma2(x2,w0.x,acc[0]); acc[1]=fma2(x2,w0.y,acc[1]);
        acc[2]=fma2(x2,w1.x,acc[2]); acc[3]=fma2(x2,w1.y,acc[3]);
        acc[4]=fma2(x2,w2.x,acc[4]); acc[5]=fma2(x2,w2.y,acc[5]);
    }
    float o12[12];
    #pragma unroll
    for (int t=0;t<6;t++) unpack2(acc[t], o12[2*t], o12[2*t+1]);
    const int p = pg + pos;
    #pragma unroll
    for (int t=0;t<12;t++) {
        int o = wq*12 + t;
        if (o < 8)       g_q[(n*8  + o     )*PP + p] = o12[t];
        else if (o < 16) g_k[(n*8  + (o-8) )*PP + p] = o12[t];
        else             g_v[(n*32 + (o-16))*PP + p] = fmaxf(o12[t], 0.f);
    }
}

// ---------------------------------------------------------------------------
// Visual attention, split-K ([c2][j] smem layout — the known-good round-11 one).
// FROZEN: two re-layout attempts both regressed.
// ---------------------------------------------------------------------------
__global__ __launch_bounds__(128) void vis_attn_split(void)
{
    __shared__ alignas(16) u64 ksu[4*128];    // [c2][j]
    __shared__ alignas(16) u64 vsu[16*128];   // [c2][j]
    const int tid = threadIdx.x;
    const int tile = blockIdx.x / NS, split = blockIdx.x % NS;
    const int n = tile / 6, tw = tile % 6;
    const int qp = tw*384 + tid;
    const float* qb_ = g_q + n*8*PP;
    const float* kb_ = g_k + n*8*PP;
    const float* vb_ = g_v + n*32*PP;

    u64 qr[3][4];
    #pragma unroll
    for (int i=0;i<3;i++)
        #pragma unroll
        for (int r=0;r<4;r++)
            qr[i][r] = pack2(qb_[(2*r)*PP + qp + i*128], qb_[(2*r+1)*PP + qp + i*128]);

    float l[3] = {0.f, 0.f, 0.f};
    u64 vacc[3][16];
    #pragma unroll
    for (int i=0;i<3;i++)
        #pragma unroll
        for (int t=0;t<16;t++) vacc[i][t] = 0ULL;

    const u64 z = 0ULL;
    for (int ch = split*2; ch < split*2 + 2; ch++) {
        __syncthreads();
        const int base = ch*128 + tid;
        #pragma unroll
        for (int r=0;r<4;r++)  ksu[r*128+tid] = pack2(kb_[(2*r)*PP+base], kb_[(2*r+1)*PP+base]);
        #pragma unroll
        for (int t=0;t<16;t++) vsu[t*128+tid] = pack2(vb_[(2*t)*PP+base], vb_[(2*t+1)*PP+base]);
        __syncthreads();
        #pragma unroll 2
        for (int j=0;j<128;j++) {
            u64 k0 = ksu[j], k1 = ksu[128+j], k2 = ksu[256+j], k3 = ksu[384+j];
            float pr[3];
            #pragma unroll
            for (int i=0;i<3;i++) {
                u64 d = add2(fma2(qr[i][0],k0,fma2(qr[i][1],k1,z)),
                             fma2(qr[i][2],k2,fma2(qr[i][3],k3,z)));
                float lo,hi; unpack2(d,lo,hi);
                pr[i] = __expf(lo + hi);
                l[i] += pr[i];
            }
            u64 p0 = pack2(pr[0],pr[0]), p1 = pack2(pr[1],pr[1]), p2 = pack2(pr[2],pr[2]);
            #pragma unroll
            for (int t=0;t<16;t++) {
                u64 vr = vsu[t*128+j];
                vacc[0][t] = fma2(p0, vr, vacc[0][t]);
                vacc[1][t] = fma2(p1, vr, vacc[1][t]);
                vacc[2][t] = fma2(p2, vr, vacc[2][t]);
            }
        }
    }
    #pragma unroll
    for (int i=0;i<3;i++) {
        int q = n*PP + qp + i*128;
        g_pl[split*QTOT + q] = l[i];
        #pragma unroll
        for (int t=0;t<16;t++) {
            float lo,hi; unpack2(vacc[i][t], lo, hi);
            g_pv[(split*32 + 2*t  )*QTOT + q] = lo;
            g_pv[(split*32 + 2*t+1)*QTOT + q] = hi;
        }
    }
}

// ---------------------------------------------------------------------------
// Combine v4: 256 threads, 8 warps; warp wq owns channels [4wq,4wq+4).
// 36 independent partial loads per thread; 2x warps vs v2 -> ~2x lines in
// flight (fixes the regs=32 MLP cap seen in profiles).
// ---------------------------------------------------------------------------
__global__ __launch_bounds__(256) void combine_kernel(
    const float* __restrict__ cw, const float* __restrict__ cb,
    float* __restrict__ out)
{
    __shared__ alignas(16) u64 cwt[32*16];    // [c][o2]
    __shared__ alignas(16) float cbs[32];
    __shared__ alignas(16) float avs[32*33];  // [cell][c], pitch 33
    const int tid = threadIdx.x;
    const int wq = tid >> 5, cell = tid & 31;

    for (int i = tid; i < 32*16; i += 256) {
        int c = i/16, t = i%16;
        cwt[i] = pack2(cw[(2*t)*32+c], cw[(2*t+1)*32+c]);
    }
    if (tid < 32) cbs[tid] = cb[tid];

    const int gid = blockIdx.x*32 + cell;
    const int n = gid/PP, p = gid%PP;

    // reduce l over splits (redundant across the 8 wq threads of a cell)
    float l = 0.f;
    #pragma unroll
    for (int sp=0; sp<NS; sp++) l += g_pl[sp*QTOT + gid];

    // reduce this thread's 4 channels over splits (36 independent coalesced loads)
    float va[4];
    #pragma unroll
    for (int j=0;j<4;j++) va[j] = 0.f;
    #pragma unroll
    for (int sp=0; sp<NS; sp++) {
        #pragma unroll
        for (int j=0;j<4;j++)
            va[j] += g_pv[(sp*32 + wq*4 + j)*QTOT + gid];
    }
    float inv = 1.f / l;
    #pragma unroll
    for (int j=0;j<4;j++) avs[cell*33 + wq*4 + j] = va[j] * inv;
    __syncthreads();

    // conv 32->32: warp wq computes outputs [4wq,4wq+4) for its cell
    u64 acc[2];
    {
        const u64* bp = (const u64*)cbs;
        acc[0] = bp[wq*2]; acc[1] = bp[wq*2+1];
    }
    #pragma unroll 8
    for (int c=0;c<32;c++) {
        float av = avs[cell*33 + c];
        u64 x2 = pack2(av, av);
        const ulonglong2* wr = (const ulonglong2*)(cwt + c*16 + wq*2);
        ulonglong2 w = wr[0];
        acc[0]=fma2(x2,w.x,acc[0]); acc[1]=fma2(x2,w.y,acc[1]);
    }
    float oc[4];
    unpack2(acc[0], oc[0], oc[1]);
    unpack2(acc[1], oc[2], oc[3]);

    // own 4 channels of v (coalesced LDG)
    float vv[4];
    #pragma unroll
    for (int j=0;j<4;j++) vv[j] = g_v[(n*32 + wq*4 + j)*PP + p];

    float* ob = out + (long)n*NSTRIDE + p;   // slice 0
    #pragma unroll
    for (int j=0;j<4;j++) {
        ob[(wq*4+j)*PP]      = oc[j];
        ob[(32+wq*4+j)*PP]   = vv[j];
    }

    float* xp = g_x + ((long)p*8 + n)*64;
    *(float4*)(xp + wq*4)      = make_float4(oc[0],oc[1],oc[2],oc[3]);
    *(float4*)(xp + 32 + wq*4) = make_float4(vv[0],vv[1],vv[2],vv[3]);
}

// ---------------------------------------------------------------------------
// MEGA temporal v5 (unchanged from the 144 us version).
// ---------------------------------------------------------------------------
__global__ __launch_bounds__(128) void mega_temporal(
    const float* __restrict__ tq_b, const float* __restrict__ tk_b,
    const float* __restrict__ tv_b, const float* __restrict__ tc_b,
    float* __restrict__ out)
{
    __shared__ alignas(16) float swt[64*48];     // qkv weights [c][o] pitch 48
    __shared__ alignas(16) float cwt[32*32];     // conv weights [c][o] pitch 32
    __shared__ alignas(16) float sbs[48];
    __shared__ alignas(16) float cbs[32];
    __shared__ alignas(16) float xsm[64*68];     // head input [cell][c], pitch 68
    __shared__ alignas(16) float qkvsm[66*52];   // rows 0,1 = zero guards; row(cell)=2+cell

    const int tid  = threadIdx.x;
    const int wq   = tid >> 5, cp = tid & 31;
    const int posA = cp >> 3, n = cp & 7;
    const int cellA = cp, cellB = cp + 32;
    const int rowA = 2 + cellA, rowB = 2 + cellB;
    const int pg   = blockIdx.x*8;

    for (int i = tid; i < 66*52; i += 128) qkvsm[i] = 0.f;

    {
        const float* gA = g_x + ((long)(pg+posA  )*8 + n)*64 + wq*16;
        const float* gB = g_x + ((long)(pg+posA+4)*8 + n)*64 + wq*16;
        #pragma unroll
        for (int k=0;k<4;k++) {
            *(float4*)(xsm + cellA*68 + wq*16 + 4*k) = *(const float4*)(gA + 4*k);
            *(float4*)(xsm + cellB*68 + wq*16 + 4*k) = *(const float4*)(gB + 4*k);
        }
    }

    for (int h=0; h<5; h++) {
        __syncthreads();   // barrier A

        {
            const float4* wt4 = (const float4*)(g_wt + h*4096);
            float4* s4 = (float4*)swt;
            float4* c4p = (float4*)cwt;
            #pragma unroll
            for (int k=0;k<6;k++) s4[tid + 128*k] = wt4[tid + 128*k];
            #pragma unroll
            for (int k=0;k<2;k++) c4p[tid + 128*k] = wt4[768 + tid + 128*k];
        }
        if (tid < 48) sbs[tid] = (tid<8)? tq_b[h*8+tid] : (tid<16? tk_b[h*8+tid-8] : tv_b[h*32+tid-16]);
        if (tid < 32) cbs[tid] = tc_b[h*32+tid];
        __syncthreads();   // barrier B

        u64 accA[6], accB[6];
        {
            const u64* bp = (const u64*)sbs;
            #pragma unroll
            for (int t=0;t<6;t++) { accA[t] = bp[wq*6 + t]; accB[t] = accA[t]; }
        }
        #pragma unroll
        for (int c4=0; c4<64; c4+=4) {
            float4 xa = *(const float4*)(xsm + cellA*68 + c4);
            float4 xb = *(const float4*)(xsm + cellB*68 + c4);
            float xas[4] = {xa.x, xa.y, xa.z, xa.w};
            float xbs[4] = {xb.x, xb.y, xb.z, xb.w};
            #pragma unroll
            for (int j=0;j<4;j++) {
                u64 x2a = pack2(xas[j], xas[j]);
                u64 x2b = pack2(xbs[j], xbs[j]);
                const ulonglong2* wr = (const ulonglong2*)(swt + (c4+j)*48 + wq*12);
                ulonglong2 w0 = wr[0], w1 = wr[1], w2 = wr[2];
                accA[0]=fma2(x2a,w0.x,accA[0]); accA[1]=fma2(x2a,w0.y,accA[1]);
                accA[2]=fma2(x2a,w1.x,accA[2]); accA[3]=fma2(x2a,w1.y,accA[3]);
                accA[4]=fma2(x2a,w2.x,accA[4]); accA[5]=fma2(x2a,w2.y,accA[5]);
                accB[0]=fma2(x2b,w0.x,accB[0]); accB[1]=fma2(x2b,w0.y,accB[1]);
                accB[2]=fma2(x2b,w1.x,accB[2]); accB[3]=fma2(x2b,w1.y,accB[3]);
                accB[4]=fma2(x2b,w2.x,accB[4]); accB[5]=fma2(x2b,w2.y,accB[5]);
            }
        }
        {
            float oA[12], oB[12];
            #pragma unroll
            for (int t=0;t<6;t++) { unpack2(accA[t], oA[2*t], oA[2*t+1]);
                                    unpack2(accB[t], oB[2*t], oB[2*t+1]); }
            #pragma unroll
            for (int t=0;t<12;t++) if (12*wq + t >= 16) {
                oA[t] = fmaxf(oA[t], 0.f); oB[t] = fmaxf(oB[t], 0.f);
            }
            float* ra = qkvsm + rowA*52 + wq*12;
            float* rb = qkvsm + rowB*52 + wq*12;
            *(float4*)(ra  ) = make_float4(oA[0],oA[1],oA[2],oA[3]);
            *(float4*)(ra+4) = make_float4(oA[4],oA[5],oA[6],oA[7]);
            *(float4*)(ra+8) = make_float4(oA[8],oA[9],oA[10],oA[11]);
            *(float4*)(rb  ) = make_float4(oB[0],oB[1],oB[2],oB[3]);
            *(float4*)(rb+4) = make_float4(oB[4],oB[5],oB[6],oB[7]);
            *(float4*)(rb+8) = make_float4(oB[8],oB[9],oB[10],oB[11]);
        }
        __syncthreads();   // barrier C

        float a0A,a1A,a2A, a0B,a1B,a2B;
        {
            const float* rp = qkvsm + rowA*52;
            float4 q0=*(const float4*)(rp),     q1=*(const float4*)(rp+4);
            float4 k0a=*(const float4*)(rp+8),  k0b=*(const float4*)(rp+12);
            float4 k1a=*(const float4*)(rp+8-52),  k1b=*(const float4*)(rp+12-52);
            float4 k2a=*(const float4*)(rp+8-104), k2b=*(const float4*)(rp+12-104);
            float l2 = dot4(q0,k0a)+dot4(q1,k0b);
            float l1 = (n>=1) ? dot4(q0,k1a)+dot4(q1,k1b) : 0.f;
            float l0 = (n>=2) ? dot4(q0,k2a)+dot4(q1,k2b) : 0.f;
            float m  = fmaxf(l0, fmaxf(l1, l2));
            float e0=__expf(l0-m), e1=__expf(l1-m), e2=__expf(l2-m);
            float inv = 1.f/(e0+e1+e2);
            a2A = e2*inv;
            a1A = (n>=1) ? e1*inv : 0.f;
            a0A = (n>=2) ? e0*inv : 0.f;
        }
        {
            const float* rp = qkvsm + rowB*52;
            float4 q0=*(const float4*)(rp),     q1=*(const float4*)(rp+4);
            float4 k0a=*(const float4*)(rp+8),  k0b=*(const float4*)(rp+12);
            float4 k1a=*(const float4*)(rp+8-52),  k1b=*(const float4*)(rp+12-52);
            float4 k2a=*(const float4*)(rp+8-104), k2b=*(const float4*)(rp+12-104);
            float l2 = dot4(q0,k0a)+dot4(q1,k0b);
            float l1 = (n>=1) ? dot4(q0,k1a)+dot4(q1,k1b) : 0.f;
            float l0 = (n>=2) ? dot4(q0,k2a)+dot4(q1,k2b) : 0.f;
            float m  = fmaxf(l0, fmaxf(l1, l2));
            float e0=__expf(l0-m), e1=__expf(l1-m), e2=__expf(l2-m);
            float inv = 1.f/(e0+e1+e2);
            a2B = e2*inv;
            a1B = (n>=1) ? e1*inv : 0.f;
            a0B = (n>=2) ? e0*inv : 0.f;
        }

        u64 cA[4], cB[4];
        {
            const u64* bp = (const u64*)cbs;
            #pragma unroll
            for (int t=0;t<4;t++) { cA[t] = bp[wq*4 + t]; cB[t] = cA[t]; }
        }
        #pragma unroll
        for (int c4=0; c4<32; c4+=4) {
            const float* vra = qkvsm + rowA*52 + 16 + c4;
            const float* vrb = qkvsm + rowB*52 + 16 + c4;
            float4 v0a=*(const float4*)(vra), v1a=*(const float4*)(vra-52), v2a=*(const float4*)(vra-104);
            float4 v0b=*(const float4*)(vrb), v1b=*(const float4*)(vrb-52), v2b=*(const float4*)(vrb-104);
            float avA[4], avB[4];
            avA[0]=a2A*v0a.x+a1A*v1a.x+a0A*v2a.x; avA[1]=a2A*v0a.y+a1A*v1a.y+a0A*v2a.y;
            avA[2]=a2A*v0a.z+a1A*v1a.z+a0A*v2a.z; avA[3]=a2A*v0a.w+a1A*v1a.w+a0A*v2a.w;
            avB[0]=a2B*v0b.x+a1B*v1b.x+a0B*v2b.x; avB[1]=a2B*v0b.y+a1B*v1b.y+a0B*v2b.y;
            avB[2]=a2B*v0b.z+a1B*v1b.z+a0B*v2b.z; avB[3]=a2B*v0b.w+a1B*v1b.w+a0B*v2b.w;
            #pragma unroll
            for (int j=0;j<4;j++) {
                u64 x2a = pack2(avA[j], avA[j]);
                u64 x2b = pack2(avB[j], avB[j]);
                const ulonglong2* wr = (const ulonglong2*)(cwt + (c4+j)*32 + wq*8);
                ulonglong2 w0 = wr[0], w1 = wr[1];
                cA[0]=fma2(x2a,w0.x,cA[0]); cA[1]=fma2(x2a,w0.y,cA[1]);
                cA[2]=fma2(x2a,w1.x,cA[2]); cA[3]=fma2(x2a,w1.y,cA[3]);
                cB[0]=fma2(x2b,w0.x,cB[0]); cB[1]=fma2(x2b,w0.y,cB[1]);
                cB[2]=fma2(x2b,w1.x,cB[2]); cB[3]=fma2(x2b,w1.y,cB[3]);
            }
        }
        {
            float ocA[8], ocB[8];
            #pragma unroll
            for (int t=0;t<4;t++) { unpack2(cA[t], ocA[2*t], ocA[2*t+1]);
                                    unpack2(cB[t], ocB[2*t], ocB[2*t+1]); }
            float4 vaA = *(const float4*)(qkvsm + rowA*52 + 16 + wq*8);
            float4 vbA = *(const float4*)(qkvsm + rowA*52 + 16 + wq*8 + 4);
            float4 vaB = *(const float4*)(qkvsm + rowB*52 + 16 + wq*8);
            float4 vbB = *(const float4*)(qkvsm + rowB*52 + 16 + wq*8 + 4);
            float vqA[8] = {vaA.x,vaA.y,vaA.z,vaA.w, vbA.x,vbA.y,vbA.z,vbA.w};
            float vqB[8] = {vaB.x,vaB.y,vaB.z,vaB.w, vbB.x,vbB.y,vbB.z,vbB.w};

            float* obA = out + (long)n*NSTRIDE + (long)(h+1)*SLICE + pg + posA;
            float* obB = obA + 4;
            #pragma unroll
            for (int j=0;j<8;j++) {
                obA[(8*wq+j)*PP]    = ocA[j];
                obA[(32+8*wq+j)*PP] = vqA[j];
                obB[(8*wq+j)*PP]    = ocB[j];
                obB[(32+8*wq+j)*PP] = vqB[j];
            }
            float* xrA = xsm + cellA*68;
            float* xrB = xsm + cellB*68;
            *(float4*)(xrA + 8*wq    ) = make_float4(ocA[0],ocA[1],ocA[2],ocA[3]);
            *(float4*)(xrA + 8*wq + 4) = make_float4(ocA[4],ocA[5],ocA[6],ocA[7]);
            *(float4*)(xrA + 32 + 8*wq    ) = vaA;
            *(float4*)(xrA + 32 + 8*wq + 4) = vbA;
            *(float4*)(xrB + 8*wq    ) = make_float4(ocB[0],ocB[1],ocB[2],ocB[3]);
            *(float4*)(xrB + 8*wq + 4) = make_float4(ocB[4],ocB[5],ocB[6],ocB[7]);
            *(float4*)(xrB + 32 + 8*wq    ) = vaB;
            *(float4*)(xrB + 32 + 8*wq + 4) = vbB;
        }
    }
}

// ---------------------------------------------------------------------------
extern "C" void kernel_launch(void* const* d_in, const int* in_sizes, int n_in,
                              void* d_out, int out_size)
{
    const float* x    = (const float*)d_in[0];
    const float* vq_w = (const float*)d_in[1];
    const float* vq_b = (const float*)d_in[2];
    const float* vk_w = (const float*)d_in[3];
    const float* vk_b = (const float*)d_in[4];
    const float* vv_w = (const float*)d_in[5];
    const float* vv_b = (const float*)d_in[6];
    const float* vc_w = (const float*)d_in[7];
    const float* vc_b = (const float*)d_in[8];
    const float* tq_w = (const float*)d_in[9];
    const float* tq_b = (const float*)d_in[10];
    const float* tk_w = (const float*)d_in[11];
    const float* tk_b = (const float*)d_in[12];
    const float* tv_w = (const float*)d_in[13];
    const float* tv_b = (const float*)d_in[14];
    const float* tc_w = (const float*)d_in[15];
    const float* tc_b = (const float*)d_in[16];
    float* out = (float*)d_out;

    transpose_w<<<80,256>>>(tq_w, tk_w, tv_w, tc_w);
    qkv0_kernel<<<576,128>>>(x, vq_w, vq_b, vk_w, vk_b, vv_w, vv_b);
    vis_attn_split<<<48*NS,128>>>();
    combine_kernel<<<576,256>>>(vc_w, vc_b, out);
    mega_temporal<<<288,128>>>(tq_b, tk_b, tv_b, tc_b, out);
}

// round 15
// speedup vs baseline: 1.0882x; 1.0306x over previous
#include <cuda_runtime.h>

#define NB 8
#define PP 2304
#define QTOT (NB*PP)       // 18432
#define CIN 64
#define OUTC 384
#define NSTRIDE (OUTC*PP)
#define SLICE (64*PP)
#define NS 9               // split-K factor for visual attention
#define COLW 56            // (qkv0 only) smem row width

// Scratch (allocation-free rule: __device__ globals)
__device__ float g_q[NB*8*PP];
__device__ float g_k[NB*8*PP];
__device__ float g_v[NB*32*PP];
__device__ float g_pl[NS*QTOT];
__device__ float g_pv[NS*32*QTOT];   // [split][c][q] — warp-coalesced
__device__ float g_x[QTOT*64];       // [p][n][c] mega-kernel input
__device__ float g_wt[5*4096];       // per head: [64][48] qkv-T (3072) + [32][32] conv-T (1024)

typedef unsigned long long u64;

__device__ __forceinline__ u64 fma2(u64 a,u64 b,u64 c){u64 d;asm("fma.rn.f32x2 %0,%1,%2,%3;":"=l"(d):"l"(a),"l"(b),"l"(c));return d;}
__device__ __forceinline__ u64 add2(u64 a,u64 b){u64 d;asm("add.rn.f32x2 %0,%1,%2;":"=l"(d):"l"(a),"l"(b));return d;}
__device__ __forceinline__ u64 pack2(float lo,float hi){u64 d;asm("mov.b64 %0,{%1,%2};":"=l"(d):"f"(lo),"f"(hi));return d;}
__device__ __forceinline__ void unpack2(u64 v,float&lo,float&hi){asm("mov.b64 {%0,%1},%2;":"=f"(lo),"=f"(hi):"l"(v));}
__device__ __forceinline__ float ex2f(float x){float y;asm("ex2.approx.ftz.f32 %0,%1;":"=f"(y):"f"(x));return y;}

__device__ __forceinline__ float dot4(float4 a, float4 b){
    return a.x*b.x + a.y*b.y + a.z*b.z + a.w*b.w;
}

// ---------------------------------------------------------------------------
// One-shot weight transpose: [o][c] (gmem) -> [c][o] flat per head in g_wt.
// ---------------------------------------------------------------------------
__global__ __launch_bounds__(256) void transpose_w(
    const float* __restrict__ tq_w, const float* __restrict__ tk_w,
    const float* __restrict__ tv_w, const float* __restrict__ tc_w)
{
    int i = blockIdx.x*256 + threadIdx.x;
    if (i >= 5*4096) return;
    int h = i >> 12, r = i & 4095;
    float v;
    if (r < 3072) {
        int c = r / 48, o = r % 48;
        v = (o<8)  ? tq_w[h*512  + o*64 + c]
          : (o<16) ? tk_w[h*512  + (o-8)*64 + c]
                   : tv_w[h*2048 + (o-16)*64 + c];
    } else {
        int rr = r - 3072;
        int c = rr >> 5, o = rr & 31;
        v = tc_w[h*1024 + o*32 + c];
    }
    g_wt[i] = v;
}

// ---------------------------------------------------------------------------
// Stage-0 QKV, 4-way split (unchanged).
// ---------------------------------------------------------------------------
__global__ __launch_bounds__(128) void qkv0_kernel(
    const float* __restrict__ src,
    const float* __restrict__ qw, const float* __restrict__ qb,
    const float* __restrict__ kw, const float* __restrict__ kb,
    const float* __restrict__ vw, const float* __restrict__ vb)
{
    __shared__ alignas(16) float swt[64*52];
    __shared__ alignas(16) float sbs[48];
    __shared__ alignas(16) float xsm[64*COLW];

    const int tid = threadIdx.x;
    const int wq = tid >> 5, l = tid & 31;
    const int pos = l & 3, n = l >> 2;
    const int col = 8 + pos*12 + n;
    const int pg = blockIdx.x*4;

    for (int i = tid; i < 48*64; i += 128) {
        int o = i >> 6, c = i & 63;
        float wv = (o<8) ? qw[o*64+c] : (o<16) ? kw[(o-8)*64+c] : vw[(o-16)*64+c];
        swt[c*52 + o] = wv;
    }
    if (tid < 48) sbs[tid] = (tid<8)? qb[tid] : (tid<16? kb[tid-8] : vb[tid-16]);
    for (int i = tid; i < 64*32; i += 128) {
        int c = i >> 5, ce = i & 31;
        int pp_ = ce & 3, nn = ce >> 2;
        xsm[c*COLW + (8 + pp_*12 + nn)] = src[(long)nn*CIN*PP + (long)c*PP + pg + pp_];
    }
    __syncthreads();

    u64 acc[6];
    {
        const u64* bp = (const u64*)sbs;
        #pragma unroll
        for (int t=0;t<6;t++) acc[t] = bp[wq*6 + t];
    }
    #pragma unroll 8
    for (int c=0;c<64;c++) {
        float xv = xsm[c*COLW + col];
        u64 x2 = pack2(xv,xv);
        const ulonglong2* wr = (const ulonglong2*)(swt + c*52 + wq*12);
        ulonglong2 w0 = wr[0], w1 = wr[1], w2 = wr[2];
        acc[0]=fma2(x2,w0.x,acc[0]); acc[1]=fma2(x2,w0.y,acc[1]);
        acc[2]=fma2(x2,w1.x,acc[2]); acc[3]=fma2(x2,w1.y,acc[3]);
        acc[4]=fma2(x2,w2.x,acc[4]); acc[5]=fma2(x2,w2.y,acc[5]);
    }
    float o12[12];
    #pragma unroll
    for (int t=0;t<6;t++) unpack2(acc[t], o12[2*t], o12[2*t+1]);
    const int p = pg + pos;
    #pragma unroll
    for (int t=0;t<12;t++) {
        int o = wq*12 + t;
        if (o < 8)       g_q[(n*8  + o     )*PP + p] = o12[t];
        else if (o < 16) g_k[(n*8  + (o-8) )*PP + p] = o12[t];
        else             g_v[(n*32 + (o-16))*PP + p] = fmaxf(o12[t], 0.f);
    }
}

// ---------------------------------------------------------------------------
// Visual attention, split-K ([c2][j] smem layout — FROZEN).
// Change: Q pre-scaled by log2(e) at load; exp = bare ex2.approx (saves the
// FMUL inside __expf and shortens the chain before MUFU). Same softmax math.
// ---------------------------------------------------------------------------
__global__ __launch_bounds__(128) void vis_attn_split(void)
{
    __shared__ alignas(16) u64 ksu[4*128];    // [c2][j]
    __shared__ alignas(16) u64 vsu[16*128];   // [c2][j]
    const int tid = threadIdx.x;
    const int tile = blockIdx.x / NS, split = blockIdx.x % NS;
    const int n = tile / 6, tw = tile % 6;
    const int qp = tw*384 + tid;
    const float* qb_ = g_q + n*8*PP;
    const float* kb_ = g_k + n*8*PP;
    const float* vb_ = g_v + n*32*PP;
    const float L2E = 1.4426950408889634f;

    u64 qr[3][4];
    #pragma unroll
    for (int i=0;i<3;i++)
        #pragma unroll
        for (int r=0;r<4;r++)
            qr[i][r] = pack2(qb_[(2*r)*PP + qp + i*128]*L2E, qb_[(2*r+1)*PP + qp + i*128]*L2E);

    float l[3] = {0.f, 0.f, 0.f};
    u64 vacc[3][16];
    #pragma unroll
    for (int i=0;i<3;i++)
        #pragma unroll
        for (int t=0;t<16;t++) vacc[i][t] = 0ULL;

    const u64 z = 0ULL;
    for (int ch = split*2; ch < split*2 + 2; ch++) {
        __syncthreads();
        const int base = ch*128 + tid;
        #pragma unroll
        for (int r=0;r<4;r++)  ksu[r*128+tid] = pack2(kb_[(2*r)*PP+base], kb_[(2*r+1)*PP+base]);
        #pragma unroll
        for (int t=0;t<16;t++) vsu[t*128+tid] = pack2(vb_[(2*t)*PP+base], vb_[(2*t+1)*PP+base]);
        __syncthreads();
        #pragma unroll 2
        for (int j=0;j<128;j++) {
            u64 k0 = ksu[j], k1 = ksu[128+j], k2 = ksu[256+j], k3 = ksu[384+j];
            float pr[3];
            #pragma unroll
            for (int i=0;i<3;i++) {
                u64 d = add2(fma2(qr[i][0],k0,fma2(qr[i][1],k1,z)),
                             fma2(qr[i][2],k2,fma2(qr[i][3],k3,z)));
                float lo,hi; unpack2(d,lo,hi);
                pr[i] = ex2f(lo + hi);
                l[i] += pr[i];
            }
            u64 p0 = pack2(pr[0],pr[0]), p1 = pack2(pr[1],pr[1]), p2 = pack2(pr[2],pr[2]);
            #pragma unroll
            for (int t=0;t<16;t++) {
                u64 vr = vsu[t*128+j];
                vacc[0][t] = fma2(p0, vr, vacc[0][t]);
                vacc[1][t] = fma2(p1, vr, vacc[1][t]);
                vacc[2][t] = fma2(p2, vr, vacc[2][t]);
            }
        }
    }
    #pragma unroll
    for (int i=0;i<3;i++) {
        int q = n*PP + qp + i*128;
        g_pl[split*QTOT + q] = l[i];
        #pragma unroll
        for (int t=0;t<16;t++) {
            float lo,hi; unpack2(vacc[i][t], lo, hi);
            g_pv[(split*32 + 2*t  )*QTOT + q] = lo;
            g_pv[(split*32 + 2*t+1)*QTOT + q] = hi;
        }
    }
}

// ---------------------------------------------------------------------------
// Combine v5: 512 threads, 16 warps; warp wq owns channels [2wq,2wq+2).
// 18 independent partial loads/thread; 2x warps vs v4.
// ---------------------------------------------------------------------------
__global__ __launch_bounds__(512) void combine_kernel(
    const float* __restrict__ cw, const float* __restrict__ cb,
    float* __restrict__ out)
{
    __shared__ alignas(16) u64 cwt[32*16];    // [c][o2]
    __shared__ alignas(16) float cbs[32];
    __shared__ alignas(16) float avs[32*33];  // [cell][c], pitch 33
    const int tid = threadIdx.x;
    const int wq = tid >> 5, cell = tid & 31;

    for (int i = tid; i < 32*16; i += 512) {
        int c = i/16, t = i%16;
        cwt[i] = pack2(cw[(2*t)*32+c], cw[(2*t+1)*32+c]);
    }
    if (tid < 32) cbs[tid] = cb[tid];

    const int gid = blockIdx.x*32 + cell;
    const int n = gid/PP, p = gid%PP;

    // reduce l over splits (redundant across the 16 wq threads of a cell)
    float l = 0.f;
    #pragma unroll
    for (int sp=0; sp<NS; sp++) l += g_pl[sp*QTOT + gid];

    // reduce this thread's 2 channels over splits (18 independent coalesced loads)
    float va0 = 0.f, va1 = 0.f;
    #pragma unroll
    for (int sp=0; sp<NS; sp++) {
        va0 += g_pv[(sp*32 + wq*2    )*QTOT + gid];
        va1 += g_pv[(sp*32 + wq*2 + 1)*QTOT + gid];
    }
    float inv = 1.f / l;
    avs[cell*33 + wq*2    ] = va0 * inv;
    avs[cell*33 + wq*2 + 1] = va1 * inv;
    __syncthreads();

    // conv 32->32: warp wq computes outputs [2wq,2wq+2) for its cell
    u64 acc = ((const u64*)cbs)[wq];
    #pragma unroll 8
    for (int c=0;c<32;c++) {
        float av = avs[cell*33 + c];
        u64 x2 = pack2(av, av);
        acc = fma2(x2, cwt[c*16 + wq], acc);
    }
    float oc0, oc1;
    unpack2(acc, oc0, oc1);

    // own 2 channels of v (coalesced LDG)
    float vv0 = g_v[(n*32 + wq*2    )*PP + p];
    float vv1 = g_v[(n*32 + wq*2 + 1)*PP + p];

    float* ob = out + (long)n*NSTRIDE + p;   // slice 0
    ob[(wq*2  )*PP]    = oc0;
    ob[(wq*2+1)*PP]    = oc1;
    ob[(32+wq*2  )*PP] = vv0;
    ob[(32+wq*2+1)*PP] = vv1;

    float* xp = g_x + ((long)p*8 + n)*64;
    *(float2*)(xp + wq*2)      = make_float2(oc0, oc1);
    *(float2*)(xp + 32 + wq*2) = make_float2(vv0, vv1);
}

// ---------------------------------------------------------------------------
// MEGA temporal v5 (unchanged from the 143.5 us version).
// ---------------------------------------------------------------------------
__global__ __launch_bounds__(128) void mega_temporal(
    const float* __restrict__ tq_b, const float* __restrict__ tk_b,
    const float* __restrict__ tv_b, const float* __restrict__ tc_b,
    float* __restrict__ out)
{
    __shared__ alignas(16) float swt[64*48];     // qkv weights [c][o] pitch 48
    __shared__ alignas(16) float cwt[32*32];     // conv weights [c][o] pitch 32
    __shared__ alignas(16) float sbs[48];
    __shared__ alignas(16) float cbs[32];
    __shared__ alignas(16) float xsm[64*68];     // head input [cell][c], pitch 68
    __shared__ alignas(16) float qkvsm[66*52];   // rows 0,1 = zero guards; row(cell)=2+cell

    const int tid  = threadIdx.x;
    const int wq   = tid >> 5, cp = tid & 31;
    const int posA = cp >> 3, n = cp & 7;
    const int cellA = cp, cellB = cp + 32;
    const int rowA = 2 + cellA, rowB = 2 + cellB;
    const int pg   = blockIdx.x*8;

    for (int i = tid; i < 66*52; i += 128) qkvsm[i] = 0.f;

    {
        const float* gA = g_x + ((long)(pg+posA  )*8 + n)*64 + wq*16;
        const float* gB = g_x + ((long)(pg+posA+4)*8 + n)*64 + wq*16;
        #pragma unroll
        for (int k=0;k<4;k++) {
            *(float4*)(xsm + cellA*68 + wq*16 + 4*k) = *(const float4*)(gA + 4*k);
            *(float4*)(xsm + cellB*68 + wq*16 + 4*k) = *(const float4*)(gB + 4*k);
        }
    }

    for (int h=0; h<5; h++) {
        __syncthreads();   // barrier A

        {
            const float4* wt4 = (const float4*)(g_wt + h*4096);
            float4* s4 = (float4*)swt;
            float4* c4p = (float4*)cwt;
            #pragma unroll
            for (int k=0;k<6;k++) s4[tid + 128*k] = wt4[tid + 128*k];
            #pragma unroll
            for (int k=0;k<2;k++) c4p[tid + 128*k] = wt4[768 + tid + 128*k];
        }
        if (tid < 48) sbs[tid] = (tid<8)? tq_b[h*8+tid] : (tid<16? tk_b[h*8+tid-8] : tv_b[h*32+tid-16]);
        if (tid < 32) cbs[tid] = tc_b[h*32+tid];
        __syncthreads();   // barrier B

        u64 accA[6], accB[6];
        {
            const u64* bp = (const u64*)sbs;
            #pragma unroll
            for (int t=0;t<6;t++) { accA[t] = bp[wq*6 + t]; accB[t] = accA[t]; }
        }
        #pragma unroll
        for (int c4=0; c4<64; c4+=4) {
            float4 xa = *(const float4*)(xsm + cellA*68 + c4);
            float4 xb = *(const float4*)(xsm + cellB*68 + c4);
            float xas[4] = {xa.x, xa.y, xa.z, xa.w};
            float xbs[4] = {xb.x, xb.y, xb.z, xb.w};
            #pragma unroll
            for (int j=0;j<4;j++) {
                u64 x2a = pack2(xas[j], xas[j]);
                u64 x2b = pack2(xbs[j], xbs[j]);
                const ulonglong2* wr = (const ulonglong2*)(swt + (c4+j)*48 + wq*12);
                ulonglong2 w0 = wr[0], w1 = wr[1], w2 = wr[2];
                accA[0]=fma2(x2a,w0.x,accA[0]); accA[1]=fma2(x2a,w0.y,accA[1]);
                accA[2]=fma2(x2a,w1.x,accA[2]); accA[3]=fma2(x2a,w1.y,accA[3]);
                accA[4]=fma2(x2a,w2.x,accA[4]); accA[5]=fma2(x2a,w2.y,accA[5]);
                accB[0]=fma2(x2b,w0.x,accB[0]); accB[1]=fma2(x2b,w0.y,accB[1]);
                accB[2]=fma2(x2b,w1.x,accB[2]); accB[3]=fma2(x2b,w1.y,accB[3]);
                accB[4]=fma2(x2b,w2.x,accB[4]); accB[5]=fma2(x2b,w2.y,accB[5]);
            }
        }
        {
            float oA[12], oB[12];
            #pragma unroll
            for (int t=0;t<6;t++) { unpack2(accA[t], oA[2*t], oA[2*t+1]);
                                    unpack2(accB[t], oB[2*t], oB[2*t+1]); }
            #pragma unroll
            for (int t=0;t<12;t++) if (12*wq + t >= 16) {
                oA[t] = fmaxf(oA[t], 0.f); oB[t] = fmaxf(oB[t], 0.f);
            }
            float* ra = qkvsm + rowA*52 + wq*12;
            float* rb = qkvsm + rowB*52 + wq*12;
            *(float4*)(ra  ) = make_float4(oA[0],oA[1],oA[2],oA[3]);
            *(float4*)(ra+4) = make_float4(oA[4],oA[5],oA[6],oA[7]);
            *(float4*)(ra+8) = make_float4(oA[8],oA[9],oA[10],oA[11]);
            *(float4*)(rb  ) = make_float4(oB[0],oB[1],oB[2],oB[3]);
            *(float4*)(rb+4) = make_float4(oB[4],oB[5],oB[6],oB[7]);
            *(float4*)(rb+8) = make_float4(oB[8],oB[9],oB[10],oB[11]);
        }
        __syncthreads();   // barrier C

        float a0A,a1A,a2A, a0B,a1B,a2B;
        {
            const float* rp = qkvsm + rowA*52;
            float4 q0=*(const float4*)(rp),     q1=*(const float4*)(rp+4);
            float4 k0a=*(const float4*)(rp+8),  k0b=*(const float4*)(rp+12);
            float4 k1a=*(const float4*)(rp+8-52),  k1b=*(const float4*)(rp+12-52);
            float4 k2a=*(const float4*)(rp+8-104), k2b=*(const float4*)(rp+12-104);
            float l2 = dot4(q0,k0a)+dot4(q1,k0b);
            float l1 = (n>=1) ? dot4(q0,k1a)+dot4(q1,k1b) : 0.f;
            float l0 = (n>=2) ? dot4(q0,k2a)+dot4(q1,k2b) : 0.f;
            float m  = fmaxf(l0, fmaxf(l1, l2));
            float e0=__expf(l0-m), e1=__expf(l1-m), e2=__expf(l2-m);
            float inv = 1.f/(e0+e1+e2);
            a2A = e2*inv;
            a1A = (n>=1) ? e1*inv : 0.f;
            a0A = (n>=2) ? e0*inv : 0.f;
        }
        {
            const float* rp = qkvsm + rowB*52;
            float4 q0=*(const float4*)(rp),     q1=*(const float4*)(rp+4);
            float4 k0a=*(const float4*)(rp+8),  k0b=*(const float4*)(rp+12);
            float4 k1a=*(const float4*)(rp+8-52),  k1b=*(const float4*)(rp+12-52);
            float4 k2a=*(const float4*)(rp+8-104), k2b=*(const float4*)(rp+12-104);
            float l2 = dot4(q0,k0a)+dot4(q1,k0b);
            float l1 = (n>=1) ? dot4(q0,k1a)+dot4(q1,k1b) : 0.f;
            float l0 = (n>=2) ? dot4(q0,k2a)+dot4(q1,k2b) : 0.f;
            float m  = fmaxf(l0, fmaxf(l1, l2));
            float e0=__expf(l0-m), e1=__expf(l1-m), e2=__expf(l2-m);
            float inv = 1.f/(e0+e1+e2);
            a2B = e2*inv;
            a1B = (n>=1) ? e1*inv : 0.f;
            a0B = (n>=2) ? e0*inv : 0.f;
        }

        u64 cA[4], cB[4];
        {
            const u64* bp = (const u64*)cbs;
            #pragma unroll
            for (int t=0;t<4;t++) { cA[t] = bp[wq*4 + t]; cB[t] = cA[t]; }
        }
        #pragma unroll
        for (int c4=0; c4<32; c4+=4) {
            const float* vra = qkvsm + rowA*52 + 16 + c4;
            const float* vrb = qkvsm + rowB*52 + 16 + c4;
            float4 v0a=*(const float4*)(vra), v1a=*(const float4*)(vra-52), v2a=*(const float4*)(vra-104);
            float4 v0b=*(const float4*)(vrb), v1b=*(const float4*)(vrb-52), v2b=*(const float4*)(vrb-104);
            float avA[4], avB[4];
            avA[0]=a2A*v0a.x+a1A*v1a.x+a0A*v2a.x; avA[1]=a2A*v0a.y+a1A*v1a.y+a0A*v2a.y;
            avA[2]=a2A*v0a.z+a1A*v1a.z+a0A*v2a.z; avA[3]=a2A*v0a.w+a1A*v1a.w+a0A*v2a.w;
            avB[0]=a2B*v0b.x+a1B*v1b.x+a0B*v2b.x; avB[1]=a2B*v0b.y+a1B*v1b.y+a0B*v2b.y;
            avB[2]=a2B*v0b.z+a1B*v1b.z+a0B*v2b.z; avB[3]=a2B*v0b.w+a1B*v1b.w+a0B*v2b.w;
            #pragma unroll
            for (int j=0;j<4;j++) {
                u64 x2a = pack2(avA[j], avA[j]);
                u64 x2b = pack2(avB[j], avB[j]);
                const ulonglong2* wr = (const ulonglong2*)(cwt + (c4+j)*32 + wq*8);
                ulonglong2 w0 = wr[0], w1 = wr[1];
                cA[0]=fma2(x2a,w0.x,cA[0]); cA[1]=fma2(x2a,w0.y,cA[1]);
                cA[2]=fma2(x2a,w1.x,cA[2]); cA[3]=fma2(x2a,w1.y,cA[3]);
                cB[0]=fma2(x2b,w0.x,cB[0]); cB[1]=fma2(x2b,w0.y,cB[1]);
                cB[2]=fma2(x2b,w1.x,cB[2]); cB[3]=fma2(x2b,w1.y,cB[3]);
            }
        }
        {
            float ocA[8], ocB[8];
            #pragma unroll
            for (int t=0;t<4;t++) { unpack2(cA[t], ocA[2*t], ocA[2*t+1]);
                                    unpack2(cB[t], ocB[2*t], ocB[2*t+1]); }
            float4 vaA = *(const float4*)(qkvsm + rowA*52 + 16 + wq*8);
            float4 vbA = *(const float4*)(qkvsm + rowA*52 + 16 + wq*8 + 4);
            float4 vaB = *(const float4*)(qkvsm + rowB*52 + 16 + wq*8);
            float4 vbB = *(const float4*)(qkvsm + rowB*52 + 16 + wq*8 + 4);
            float vqA[8] = {vaA.x,vaA.y,vaA.z,vaA.w, vbA.x,vbA.y,vbA.z,vbA.w};
            float vqB[8] = {vaB.x,vaB.y,vaB.z,vaB.w, vbB.x,vbB.y,vbB.z,vbB.w};

            float* obA = out + (long)n*NSTRIDE + (long)(h+1)*SLICE + pg + posA;
            float* obB = obA + 4;
            #pragma unroll
            for (int j=0;j<8;j++) {
                obA[(8*wq+j)*PP]    = ocA[j];
                obA[(32+8*wq+j)*PP] = vqA[j];
                obB[(8*wq+j)*PP]    = ocB[j];
                obB[(32+8*wq+j)*PP] = vqB[j];
            }
            float* xrA = xsm + cellA*68;
            float* xrB = xsm + cellB*68;
            *(float4*)(xrA + 8*wq    ) = make_float4(ocA[0],ocA[1],ocA[2],ocA[3]);
            *(float4*)(xrA + 8*wq + 4) = make_float4(ocA[4],ocA[5],ocA[6],ocA[7]);
            *(float4*)(xrA + 32 + 8*wq    ) = vaA;
            *(float4*)(xrA + 32 + 8*wq + 4) = vbA;
            *(float4*)(xrB + 8*wq    ) = make_float4(ocB[0],ocB[1],ocB[2],ocB[3]);
            *(float4*)(xrB + 8*wq + 4) = make_float4(ocB[4],ocB[5],ocB[6],ocB[7]);
            *(float4*)(xrB + 32 + 8*wq    ) = vaB;
            *(float4*)(xrB + 32 + 8*wq + 4) = vbB;
        }
    }
}

// ---------------------------------------------------------------------------
extern "C" void kernel_launch(void* const* d_in, const int* in_sizes, int n_in,
                              void* d_out, int out_size)
{
    const float* x    = (const float*)d_in[0];
    const float* vq_w = (const float*)d_in[1];
    const float* vq_b = (const float*)d_in[2];
    const float* vk_w = (const float*)d_in[3];
    const float* vk_b = (const float*)d_in[4];
    const float* vv_w = (const float*)d_in[5];
    const float* vv_b = (const float*)d_in[6];
    const float* vc_w = (const float*)d_in[7];
    const float* vc_b = (const float*)d_in[8];
    const float* tq_w = (const float*)d_in[9];
    const float* tq_b = (const float*)d_in[10];
    const float* tk_w = (const float*)d_in[11];
    const float* tk_b = (const float*)d_in[12];
    const float* tv_w = (const float*)d_in[13];
    const float* tv_b = (const float*)d_in[14];
    const float* tc_w = (const float*)d_in[15];
    const float* tc_b = (const float*)d_in[16];
    float* out = (float*)d_out;

    transpose_w<<<80,256>>>(tq_w, tk_w, tv_w, tc_w);
    qkv0_kernel<<<576,128>>>(x, vq_w, vq_b, vk_w, vk_b, vv_w, vv_b);
    vis_attn_split<<<48*NS,128>>>();
    combine_kernel<<<576,512>>>(vc_w, vc_b, out);
    mega_temporal<<<288,128>>>(tq_b, tk_b, tv_b, tc_b, out);
}

// round 16
// speedup vs baseline: 1.1045x; 1.0149x over previous
#include <cuda_runtime.h>

#define NB 8
#define PP 2304
#define QTOT (NB*PP)       // 18432
#define CIN 64
#define OUTC 384
#define NSTRIDE (OUTC*PP)
#define SLICE (64*PP)
#define NS 9               // split-K factor for visual attention
#define COLW 56            // (qkv0 only) smem row width

// Scratch (allocation-free rule: __device__ globals)
__device__ float g_q[NB*8*PP];
__device__ float g_k[NB*8*PP];
__device__ float g_v[NB*32*PP];
__device__ float g_pl[NS*QTOT];
__device__ float g_pv[NS*32*QTOT];   // [split][c][q] — warp-coalesced
__device__ float g_x[QTOT*64];       // [p][n][c] mega-kernel input
__device__ float g_wt[5*4096];       // per head: [64][48] qkv-T (3072) + [32][32] conv-T (1024)

typedef unsigned long long u64;

__device__ __forceinline__ u64 fma2(u64 a,u64 b,u64 c){u64 d;asm("fma.rn.f32x2 %0,%1,%2,%3;":"=l"(d):"l"(a),"l"(b),"l"(c));return d;}
__device__ __forceinline__ u64 add2(u64 a,u64 b){u64 d;asm("add.rn.f32x2 %0,%1,%2;":"=l"(d):"l"(a),"l"(b));return d;}
__device__ __forceinline__ u64 pack2(float lo,float hi){u64 d;asm("mov.b64 %0,{%1,%2};":"=l"(d):"f"(lo),"f"(hi));return d;}
__device__ __forceinline__ void unpack2(u64 v,float&lo,float&hi){asm("mov.b64 {%0,%1},%2;":"=f"(lo),"=f"(hi):"l"(v));}
__device__ __forceinline__ float ex2f(float x){float y;asm("ex2.approx.ftz.f32 %0,%1;":"=f"(y):"f"(x));return y;}

__device__ __forceinline__ float dot4(float4 a, float4 b){
    return a.x*b.x + a.y*b.y + a.z*b.z + a.w*b.w;
}

// ---------------------------------------------------------------------------
// One-shot weight transpose: [o][c] (gmem) -> [c][o] flat per head in g_wt.
// ---------------------------------------------------------------------------
__global__ __launch_bounds__(256) void transpose_w(
    const float* __restrict__ tq_w, const float* __restrict__ tk_w,
    const float* __restrict__ tv_w, const float* __restrict__ tc_w)
{
    int i = blockIdx.x*256 + threadIdx.x;
    if (i >= 5*4096) return;
    int h = i >> 12, r = i & 4095;
    float v;
    if (r < 3072) {
        int c = r / 48, o = r % 48;
        v = (o<8)  ? tq_w[h*512  + o*64 + c]
          : (o<16) ? tk_w[h*512  + (o-8)*64 + c]
                   : tv_w[h*2048 + (o-16)*64 + c];
    } else {
        int rr = r - 3072;
        int c = rr >> 5, o = rr & 31;
        v = tc_w[h*1024 + o*32 + c];
    }
    g_wt[i] = v;
}

// ---------------------------------------------------------------------------
// Stage-0 QKV, 4-way split (unchanged).
// ---------------------------------------------------------------------------
__global__ __launch_bounds__(128) void qkv0_kernel(
    const float* __restrict__ src,
    const float* __restrict__ qw, const float* __restrict__ qb,
    const float* __restrict__ kw, const float* __restrict__ kb,
    const float* __restrict__ vw, const float* __restrict__ vb)
{
    __shared__ alignas(16) float swt[64*52];
    __shared__ alignas(16) float sbs[48];
    __shared__ alignas(16) float xsm[64*COLW];

    const int tid = threadIdx.x;
    const int wq = tid >> 5, l = tid & 31;
    const int pos = l & 3, n = l >> 2;
    const int col = 8 + pos*12 + n;
    const int pg = blockIdx.x*4;

    for (int i = tid; i < 48*64; i += 128) {
        int o = i >> 6, c = i & 63;
        float wv = (o<8) ? qw[o*64+c] : (o<16) ? kw[(o-8)*64+c] : vw[(o-16)*64+c];
        swt[c*52 + o] = wv;
    }
    if (tid < 48) sbs[tid] = (tid<8)? qb[tid] : (tid<16? kb[tid-8] : vb[tid-16]);
    for (int i = tid; i < 64*32; i += 128) {
        int c = i >> 5, ce = i & 31;
        int pp_ = ce & 3, nn = ce >> 2;
        xsm[c*COLW + (8 + pp_*12 + nn)] = src[(long)nn*CIN*PP + (long)c*PP + pg + pp_];
    }
    __syncthreads();

    u64 acc[6];
    {
        const u64* bp = (const u64*)sbs;
        #pragma unroll
        for (int t=0;t<6;t++) acc[t] = bp[wq*6 + t];
    }
    #pragma unroll 8
    for (int c=0;c<64;c++) {
        float xv = xsm[c*COLW + col];
        u64 x2 = pack2(xv,xv);
        const ulonglong2* wr = (const ulonglong2*)(swt + c*52 + wq*12);
        ulonglong2 w0 = wr[0], w1 = wr[1], w2 = wr[2];
        acc[0]=fma2(x2,w0.x,acc[0]); acc[1]=fma2(x2,w0.y,acc[1]);
        acc[2]=fma2(x2,w1.x,acc[2]); acc[3]=fma2(x2,w1.y,acc[3]);
        acc[4]=fma2(x2,w2.x,acc[4]); acc[5]=fma2(x2,w2.y,acc[5]);
    }
    float o12[12];
    #pragma unroll
    for (int t=0;t<6;t++) unpack2(acc[t], o12[2*t], o12[2*t+1]);
    const int p = pg + pos;
    #pragma unroll
    for (int t=0;t<12;t++) {
        int o = wq*12 + t;
        if (o < 8)       g_q[(n*8  + o     )*PP + p] = o12[t];
        else if (o < 16) g_k[(n*8  + (o-8) )*PP + p] = o12[t];
        else             g_v[(n*32 + (o-16))*PP + p] = fmaxf(o12[t], 0.f);
    }
}

// ---------------------------------------------------------------------------
// Visual attention, split-K ([c2][j] smem layout — FROZEN), with log2e folded
// into Q and bare ex2.approx (round-15 win, kept).
// ---------------------------------------------------------------------------
__global__ __launch_bounds__(128) void vis_attn_split(void)
{
    __shared__ alignas(16) u64 ksu[4*128];    // [c2][j]
    __shared__ alignas(16) u64 vsu[16*128];   // [c2][j]
    const int tid = threadIdx.x;
    const int tile = blockIdx.x / NS, split = blockIdx.x % NS;
    const int n = tile / 6, tw = tile % 6;
    const int qp = tw*384 + tid;
    const float* qb_ = g_q + n*8*PP;
    const float* kb_ = g_k + n*8*PP;
    const float* vb_ = g_v + n*32*PP;
    const float L2E = 1.4426950408889634f;

    u64 qr[3][4];
    #pragma unroll
    for (int i=0;i<3;i++)
        #pragma unroll
        for (int r=0;r<4;r++)
            qr[i][r] = pack2(qb_[(2*r)*PP + qp + i*128]*L2E, qb_[(2*r+1)*PP + qp + i*128]*L2E);

    float l[3] = {0.f, 0.f, 0.f};
    u64 vacc[3][16];
    #pragma unroll
    for (int i=0;i<3;i++)
        #pragma unroll
        for (int t=0;t<16;t++) vacc[i][t] = 0ULL;

    const u64 z = 0ULL;
    for (int ch = split*2; ch < split*2 + 2; ch++) {
        __syncthreads();
        const int base = ch*128 + tid;
        #pragma unroll
        for (int r=0;r<4;r++)  ksu[r*128+tid] = pack2(kb_[(2*r)*PP+base], kb_[(2*r+1)*PP+base]);
        #pragma unroll
        for (int t=0;t<16;t++) vsu[t*128+tid] = pack2(vb_[(2*t)*PP+base], vb_[(2*t+1)*PP+base]);
        __syncthreads();
        #pragma unroll 2
        for (int j=0;j<128;j++) {
            u64 k0 = ksu[j], k1 = ksu[128+j], k2 = ksu[256+j], k3 = ksu[384+j];
            float pr[3];
            #pragma unroll
            for (int i=0;i<3;i++) {
                u64 d = add2(fma2(qr[i][0],k0,fma2(qr[i][1],k1,z)),
                             fma2(qr[i][2],k2,fma2(qr[i][3],k3,z)));
                float lo,hi; unpack2(d,lo,hi);
                pr[i] = ex2f(lo + hi);
                l[i] += pr[i];
            }
            u64 p0 = pack2(pr[0],pr[0]), p1 = pack2(pr[1],pr[1]), p2 = pack2(pr[2],pr[2]);
            #pragma unroll
            for (int t=0;t<16;t++) {
                u64 vr = vsu[t*128+j];
                vacc[0][t] = fma2(p0, vr, vacc[0][t]);
                vacc[1][t] = fma2(p1, vr, vacc[1][t]);
                vacc[2][t] = fma2(p2, vr, vacc[2][t]);
            }
        }
    }
    #pragma unroll
    for (int i=0;i<3;i++) {
        int q = n*PP + qp + i*128;
        g_pl[split*QTOT + q] = l[i];
        #pragma unroll
        for (int t=0;t<16;t++) {
            float lo,hi; unpack2(vacc[i][t], lo, hi);
            g_pv[(split*32 + 2*t  )*QTOT + q] = lo;
            g_pv[(split*32 + 2*t+1)*QTOT + q] = hi;
        }
    }
}

// ---------------------------------------------------------------------------
// Combine v4 (measured best: 256 threads, warp wq owns channels [4wq,4wq+4),
// 36 independent partial loads/thread, 2 u64 conv accumulators).
// ---------------------------------------------------------------------------
__global__ __launch_bounds__(256) void combine_kernel(
    const float* __restrict__ cw, const float* __restrict__ cb,
    float* __restrict__ out)
{
    __shared__ alignas(16) u64 cwt[32*16];    // [c][o2]
    __shared__ alignas(16) float cbs[32];
    __shared__ alignas(16) float avs[32*33];  // [cell][c], pitch 33
    const int tid = threadIdx.x;
    const int wq = tid >> 5, cell = tid & 31;

    for (int i = tid; i < 32*16; i += 256) {
        int c = i/16, t = i%16;
        cwt[i] = pack2(cw[(2*t)*32+c], cw[(2*t+1)*32+c]);
    }
    if (tid < 32) cbs[tid] = cb[tid];

    const int gid = blockIdx.x*32 + cell;
    const int n = gid/PP, p = gid%PP;

    float l = 0.f;
    #pragma unroll
    for (int sp=0; sp<NS; sp++) l += g_pl[sp*QTOT + gid];

    float va[4];
    #pragma unroll
    for (int j=0;j<4;j++) va[j] = 0.f;
    #pragma unroll
    for (int sp=0; sp<NS; sp++) {
        #pragma unroll
        for (int j=0;j<4;j++)
            va[j] += g_pv[(sp*32 + wq*4 + j)*QTOT + gid];
    }
    float inv = 1.f / l;
    #pragma unroll
    for (int j=0;j<4;j++) avs[cell*33 + wq*4 + j] = va[j] * inv;
    __syncthreads();

    u64 acc[2];
    {
        const u64* bp = (const u64*)cbs;
        acc[0] = bp[wq*2]; acc[1] = bp[wq*2+1];
    }
    #pragma unroll 8
    for (int c=0;c<32;c++) {
        float av = avs[cell*33 + c];
        u64 x2 = pack2(av, av);
        const ulonglong2* wr = (const ulonglong2*)(cwt + c*16 + wq*2);
        ulonglong2 w = wr[0];
        acc[0]=fma2(x2,w.x,acc[0]); acc[1]=fma2(x2,w.y,acc[1]);
    }
    float oc[4];
    unpack2(acc[0], oc[0], oc[1]);
    unpack2(acc[1], oc[2], oc[3]);

    float vv[4];
    #pragma unroll
    for (int j=0;j<4;j++) vv[j] = g_v[(n*32 + wq*4 + j)*PP + p];

    float* ob = out + (long)n*NSTRIDE + p;   // slice 0
    #pragma unroll
    for (int j=0;j<4;j++) {
        ob[(wq*4+j)*PP]      = oc[j];
        ob[(32+wq*4+j)*PP]   = vv[j];
    }

    float* xp = g_x + ((long)p*8 + n)*64;
    *(float4*)(xp + wq*4)      = make_float4(oc[0],oc[1],oc[2],oc[3]);
    *(float4*)(xp + 32 + wq*4) = make_float4(vv[0],vv[1],vv[2],vv[3]);
}

// ---------------------------------------------------------------------------
// MEGA temporal v5 (unchanged).
// ---------------------------------------------------------------------------
__global__ __launch_bounds__(128) void mega_temporal(
    const float* __restrict__ tq_b, const float* __restrict__ tk_b,
    const float* __restrict__ tv_b, const float* __restrict__ tc_b,
    float* __restrict__ out)
{
    __shared__ alignas(16) float swt[64*48];     // qkv weights [c][o] pitch 48
    __shared__ alignas(16) float cwt[32*32];     // conv weights [c][o] pitch 32
    __shared__ alignas(16) float sbs[48];
    __shared__ alignas(16) float cbs[32];
    __shared__ alignas(16) float xsm[64*68];     // head input [cell][c], pitch 68
    __shared__ alignas(16) float qkvsm[66*52];   // rows 0,1 = zero guards; row(cell)=2+cell

    const int tid  = threadIdx.x;
    const int wq   = tid >> 5, cp = tid & 31;
    const int posA = cp >> 3, n = cp & 7;
    const int cellA = cp, cellB = cp + 32;
    const int rowA = 2 + cellA, rowB = 2 + cellB;
    const int pg   = blockIdx.x*8;

    for (int i = tid; i < 66*52; i += 128) qkvsm[i] = 0.f;

    {
        const float* gA = g_x + ((long)(pg+posA  )*8 + n)*64 + wq*16;
        const float* gB = g_x + ((long)(pg+posA+4)*8 + n)*64 + wq*16;
        #pragma unroll
        for (int k=0;k<4;k++) {
            *(float4*)(xsm + cellA*68 + wq*16 + 4*k) = *(const float4*)(gA + 4*k);
            *(float4*)(xsm + cellB*68 + wq*16 + 4*k) = *(const float4*)(gB + 4*k);
        }
    }

    for (int h=0; h<5; h++) {
        __syncthreads();   // barrier A

        {
            const float4* wt4 = (const float4*)(g_wt + h*4096);
            float4* s4 = (float4*)swt;
            float4* c4p = (float4*)cwt;
            #pragma unroll
            for (int k=0;k<6;k++) s4[tid + 128*k] = wt4[tid + 128*k];
            #pragma unroll
            for (int k=0;k<2;k++) c4p[tid + 128*k] = wt4[768 + tid + 128*k];
        }
        if (tid < 48) sbs[tid] = (tid<8)? tq_b[h*8+tid] : (tid<16? tk_b[h*8+tid-8] : tv_b[h*32+tid-16]);
        if (tid < 32) cbs[tid] = tc_b[h*32+tid];
        __syncthreads();   // barrier B

        u64 accA[6], accB[6];
        {
            const u64* bp = (const u64*)sbs;
            #pragma unroll
            for (int t=0;t<6;t++) { accA[t] = bp[wq*6 + t]; accB[t] = accA[t]; }
        }
        #pragma unroll
        for (int c4=0; c4<64; c4+=4) {
            float4 xa = *(const float4*)(xsm + cellA*68 + c4);
            float4 xb = *(const float4*)(xsm + cellB*68 + c4);
            float xas[4] = {xa.x, xa.y, xa.z, xa.w};
            float xbs[4] = {xb.x, xb.y, xb.z, xb.w};
            #pragma unroll
            for (int j=0;j<4;j++) {
                u64 x2a = pack2(xas[j], xas[j]);
                u64 x2b = pack2(xbs[j], xbs[j]);
                const ulonglong2* wr = (const ulonglong2*)(swt + (c4+j)*48 + wq*12);
                ulonglong2 w0 = wr[0], w1 = wr[1], w2 = wr[2];
                accA[0]=fma2(x2a,w0.x,accA[0]); accA[1]=fma2(x2a,w0.y,accA[1]);
                accA[2]=fma2(x2a,w1.x,accA[2]); accA[3]=fma2(x2a,w1.y,accA[3]);
                accA[4]=fma2(x2a,w2.x,accA[4]); accA[5]=fma2(x2a,w2.y,accA[5]);
                accB[0]=fma2(x2b,w0.x,accB[0]); accB[1]=fma2(x2b,w0.y,accB[1]);
                accB[2]=fma2(x2b,w1.x,accB[2]); accB[3]=fma2(x2b,w1.y,accB[3]);
                accB[4]=fma2(x2b,w2.x,accB[4]); accB[5]=fma2(x2b,w2.y,accB[5]);
            }
        }
        {
            float oA[12], oB[12];
            #pragma unroll
            for (int t=0;t<6;t++) { unpack2(accA[t], oA[2*t], oA[2*t+1]);
                                    unpack2(accB[t], oB[2*t], oB[2*t+1]); }
            #pragma unroll
            for (int t=0;t<12;t++) if (12*wq + t >= 16) {
                oA[t] = fmaxf(oA[t], 0.f); oB[t] = fmaxf(oB[t], 0.f);
            }
            float* ra = qkvsm + rowA*52 + wq*12;
            float* rb = qkvsm + rowB*52 + wq*12;
            *(float4*)(ra  ) = make_float4(oA[0],oA[1],oA[2],oA[3]);
            *(float4*)(ra+4) = make_float4(oA[4],oA[5],oA[6],oA[7]);
            *(float4*)(ra+8) = make_float4(oA[8],oA[9],oA[10],oA[11]);
            *(float4*)(rb  ) = make_float4(oB[0],oB[1],oB[2],oB[3]);
            *(float4*)(rb+4) = make_float4(oB[4],oB[5],oB[6],oB[7]);
            *(float4*)(rb+8) = make_float4(oB[8],oB[9],oB[10],oB[11]);
        }
        __syncthreads();   // barrier C

        float a0A,a1A,a2A, a0B,a1B,a2B;
        {
            const float* rp = qkvsm + rowA*52;
            float4 q0=*(const float4*)(rp),     q1=*(const float4*)(rp+4);
            float4 k0a=*(const float4*)(rp+8),  k0b=*(const float4*)(rp+12);
            float4 k1a=*(const float4*)(rp+8-52),  k1b=*(const float4*)(rp+12-52);
            float4 k2a=*(const float4*)(rp+8-104), k2b=*(const float4*)(rp+12-104);
            float l2 = dot4(q0,k0a)+dot4(q1,k0b);
            float l1 = (n>=1) ? dot4(q0,k1a)+dot4(q1,k1b) : 0.f;
            float l0 = (n>=2) ? dot4(q0,k2a)+dot4(q1,k2b) : 0.f;
            float m  = fmaxf(l0, fmaxf(l1, l2));
            float e0=__expf(l0-m), e1=__expf(l1-m), e2=__expf(l2-m);
            float inv = 1.f/(e0+e1+e2);
            a2A = e2*inv;
            a1A = (n>=1) ? e1*inv : 0.f;
            a0A = (n>=2) ? e0*inv : 0.f;
        }
        {
            const float* rp = qkvsm + rowB*52;
            float4 q0=*(const float4*)(rp),     q1=*(const float4*)(rp+4);
            float4 k0a=*(const float4*)(rp+8),  k0b=*(const float4*)(rp+12);
            float4 k1a=*(const float4*)(rp+8-52),  k1b=*(const float4*)(rp+12-52);
            float4 k2a=*(const float4*)(rp+8-104), k2b=*(const float4*)(rp+12-104);
            float l2 = dot4(q0,k0a)+dot4(q1,k0b);
            float l1 = (n>=1) ? dot4(q0,k1a)+dot4(q1,k1b) : 0.f;
            float l0 = (n>=2) ? dot4(q0,k2a)+dot4(q1,k2b) : 0.f;
            float m  = fmaxf(l0, fmaxf(l1, l2));
            float e0=__expf(l0-m), e1=__expf(l1-m), e2=__expf(l2-m);
            float inv = 1.f/(e0+e1+e2);
            a2B = e2*inv;
            a1B = (n>=1) ? e1*inv : 0.f;
            a0B = (n>=2) ? e0*inv : 0.f;
        }

        u64 cA[4], cB[4];
        {
            const u64* bp = (const u64*)cbs;
            #pragma unroll
            for (int t=0;t<4;t++) { cA[t] = bp[wq*4 + t]; cB[t] = cA[t]; }
        }
        #pragma unroll
        for (int c4=0; c4<32; c4+=4) {
            const float* vra = qkvsm + rowA*52 + 16 + c4;
            const float* vrb = qkvsm + rowB*52 + 16 + c4;
            float4 v0a=*(const float4*)(vra), v1a=*(const float4*)(vra-52), v2a=*(const float4*)(vra-104);
            float4 v0b=*(const float4*)(vrb), v1b=*(const float4*)(vrb-52), v2b=*(const float4*)(vrb-104);
            float avA[4], avB[4];
            avA[0]=a2A*v0a.x+a1A*v1a.x+a0A*v2a.x; avA[1]=a2A*v0a.y+a1A*v1a.y+a0A*v2a.y;
            avA[2]=a2A*v0a.z+a1A*v1a.z+a0A*v2a.z; avA[3]=a2A*v0a.w+a1A*v1a.w+a0A*v2a.w;
            avB[0]=a2B*v0b.x+a1B*v1b.x+a0B*v2b.x; avB[1]=a2B*v0b.y+a1B*v1b.y+a0B*v2b.y;
            avB[2]=a2B*v0b.z+a1B*v1b.z+a0B*v2b.z; avB[3]=a2B*v0b.w+a1B*v1b.w+a0B*v2b.w;
            #pragma unroll
            for (int j=0;j<4;j++) {
                u64 x2a = pack2(avA[j], avA[j]);
                u64 x2b = pack2(avB[j], avB[j]);
                const ulonglong2* wr = (const ulonglong2*)(cwt + (c4+j)*32 + wq*8);
                ulonglong2 w0 = wr[0], w1 = wr[1];
                cA[0]=fma2(x2a,w0.x,cA[0]); cA[1]=fma2(x2a,w0.y,cA[1]);
                cA[2]=fma2(x2a,w1.x,cA[2]); cA[3]=fma2(x2a,w1.y,cA[3]);
                cB[0]=fma2(x2b,w0.x,cB[0]); cB[1]=fma2(x2b,w0.y,cB[1]);
                cB[2]=fma2(x2b,w1.x,cB[2]); cB[3]=fma2(x2b,w1.y,cB[3]);
            }
        }
        {
            float ocA[8], ocB[8];
            #pragma unroll
            for (int t=0;t<4;t++) { unpack2(cA[t], ocA[2*t], ocA[2*t+1]);
                                    unpack2(cB[t], ocB[2*t], ocB[2*t+1]); }
            float4 vaA = *(const float4*)(qkvsm + rowA*52 + 16 + wq*8);
            float4 vbA = *(const float4*)(qkvsm + rowA*52 + 16 + wq*8 + 4);
            float4 vaB = *(const float4*)(qkvsm + rowB*52 + 16 + wq*8);
            float4 vbB = *(const float4*)(qkvsm + rowB*52 + 16 + wq*8 + 4);
            float vqA[8] = {vaA.x,vaA.y,vaA.z,vaA.w, vbA.x,vbA.y,vbA.z,vbA.w};
            float vqB[8] = {vaB.x,vaB.y,vaB.z,vaB.w, vbB.x,vbB.y,vbB.z,vbB.w};

            float* obA = out + (long)n*NSTRIDE + (long)(h+1)*SLICE + pg + posA;
            float* obB = obA + 4;
            #pragma unroll
            for (int j=0;j<8;j++) {
                obA[(8*wq+j)*PP]    = ocA[j];
                obA[(32+8*wq+j)*PP] = vqA[j];
                obB[(8*wq+j)*PP]    = ocB[j];
                obB[(32+8*wq+j)*PP] = vqB[j];
            }
            float* xrA = xsm + cellA*68;
            float* xrB = xsm + cellB*68;
            *(float4*)(xrA + 8*wq    ) = make_float4(ocA[0],ocA[1],ocA[2],ocA[3]);
            *(float4*)(xrA + 8*wq + 4) = make_float4(ocA[4],ocA[5],ocA[6],ocA[7]);
            *(float4*)(xrA + 32 + 8*wq    ) = vaA;
            *(float4*)(xrA + 32 + 8*wq + 4) = vbA;
            *(float4*)(xrB + 8*wq    ) = make_float4(ocB[0],ocB[1],ocB[2],ocB[3]);
            *(float4*)(xrB + 8*wq + 4) = make_float4(ocB[4],ocB[5],ocB[6],ocB[7]);
            *(float4*)(xrB + 32 + 8*wq    ) = vaB;
            *(float4*)(xrB + 32 + 8*wq + 4) = vbB;
        }
    }
}

// ---------------------------------------------------------------------------
extern "C" void kernel_launch(void* const* d_in, const int* in_sizes, int n_in,
                              void* d_out, int out_size)
{
    const float* x    = (const float*)d_in[0];
    const float* vq_w = (const float*)d_in[1];
    const float* vq_b = (const float*)d_in[2];
    const float* vk_w = (const float*)d_in[3];
    const float* vk_b = (const float*)d_in[4];
    const float* vv_w = (const float*)d_in[5];
    const float* vv_b = (const float*)d_in[6];
    const float* vc_w = (const float*)d_in[7];
    const float* vc_b = (const float*)d_in[8];
    const float* tq_w = (const float*)d_in[9];
    const float* tq_b = (const float*)d_in[10];
    const float* tk_w = (const float*)d_in[11];
    const float* tk_b = (const float*)d_in[12];
    const float* tv_w = (const float*)d_in[13];
    const float* tv_b = (const float*)d_in[14];
    const float* tc_w = (const float*)d_in[15];
    const float* tc_b = (const float*)d_in[16];
    float* out = (float*)d_out;

    transpose_w<<<80,256>>>(tq_w, tk_w, tv_w, tc_w);
    qkv0_kernel<<<576,128>>>(x, vq_w, vq_b, vk_w, vk_b, vv_w, vv_b);
    vis_attn_split<<<48*NS,128>>>();
    combine_kernel<<<576,256>>>(vc_w, vc_b, out);
    mega_temporal<<<288,128>>>(tq_b, tk_b, tv_b, tc_b, out);
}